// round 3
// baseline (speedup 1.0000x reference)
#include <cuda_runtime.h>
#include <cuda_bf16.h>
#include <math.h>

#define N_NODES 50000
#define N_EDGES 800000
#define IN_DIM  512
#define HID     256
#define OUT_DIM 128

// ---------------- scratch (static device globals; no allocation) ----------------
__device__ float    g_q[N_NODES * HID];
__device__ float    g_k[N_NODES * HID];
__device__ float    g_v[N_NODES * HID];
__device__ float    g_s[N_NODES * HID];   // skip (x@Ws+bs)
__device__ float    g_h[N_NODES * HID];   // conv out -> h1 -> conv2 out
__device__ float    g_score[N_EDGES];
__device__ float    g_w[N_EDGES];
__device__ unsigned g_mkey[N_NODES];
__device__ float    g_denom[N_NODES];
__device__ int      g_deg[N_NODES];
__device__ int      g_off[N_NODES + 1];
__device__ int      g_cursor[N_NODES];
__device__ int      g_csr[N_EDGES];
__device__ int      g_src[N_EDGES];
__device__ int      g_dst[N_EDGES];
__device__ double   g_red[2];
__device__ int      g_is64;

// ---------------- edge-index dtype detection ----------------
// If the buffer truly holds int64 indices, every int64 read is in [0, N).
// If it holds int32, int64 reads fuse adjacent pairs -> out of range somewhere.
__global__ void detect_idx_kernel(const long long* __restrict__ ei) {
    int stride = gridDim.x * blockDim.x;
    int bad = 0;
    for (int i = blockIdx.x * blockDim.x + threadIdx.x; i < 2 * N_EDGES; i += stride) {
        long long v = ei[i];
        if (v < 0 || v >= N_NODES) bad = 1;
    }
    if (__syncthreads_or(bad) && threadIdx.x == 0) atomicAnd(&g_is64, 0);
}

// ---------------- edge preprocessing ----------------
__global__ void cvt_count_kernel(const void* __restrict__ eiv) {
    const bool is64 = (g_is64 != 0);
    const long long* e64 = (const long long*)eiv;
    const int*       e32 = (const int*)eiv;
    int stride = gridDim.x * blockDim.x;
    for (int e = blockIdx.x * blockDim.x + threadIdx.x; e < N_EDGES; e += stride) {
        long long sv = is64 ? e64[e]           : (long long)e32[e];
        long long dv = is64 ? e64[N_EDGES + e] : (long long)e32[N_EDGES + e];
        int s = (int)sv, d = (int)dv;
        if (s < 0) s = 0; if (s >= N_NODES) s = N_NODES - 1;   // defensive clamp
        if (d < 0) d = 0; if (d >= N_NODES) d = N_NODES - 1;
        g_src[e] = s;
        g_dst[e] = d;
        atomicAdd(&g_deg[d], 1);
    }
}

__global__ void scan_offsets_kernel() {
    __shared__ int partial[1024];
    int t = threadIdx.x;
    const int C = (N_NODES + 1023) / 1024;  // 49
    int lo = t * C;
    int hi = lo + C; if (hi > N_NODES) hi = N_NODES;
    if (lo > N_NODES) lo = N_NODES;
    int s = 0;
    for (int i = lo; i < hi; i++) s += g_deg[i];
    partial[t] = s;
    __syncthreads();
    // Hillis-Steele inclusive scan
    for (int o = 1; o < 1024; o <<= 1) {
        int add = (t >= o) ? partial[t - o] : 0;
        __syncthreads();
        partial[t] += add;
        __syncthreads();
    }
    int run = partial[t] - s;  // exclusive prefix for this chunk
    for (int i = lo; i < hi; i++) {
        g_off[i] = run;
        g_cursor[i] = run;
        run += g_deg[i];
    }
    if (t == 1023) g_off[N_NODES] = partial[1023];
}

__global__ void fill_csr_kernel() {
    int stride = gridDim.x * blockDim.x;
    for (int e = blockIdx.x * blockDim.x + threadIdx.x; e < N_EDGES; e += stride) {
        int p = atomicAdd(&g_cursor[g_dst[e]], 1);
        if (p >= 0 && p < N_EDGES) g_csr[p] = e;
    }
}

// ---------------- SGEMM: C = A[MxK] @ B[KxN] + bias ----------------
// BM=128 BN=64 BK=16, 256 threads, TM=8 TN=4
__global__ void sgemm_bias_kernel(const float* __restrict__ A,
                                  const float* __restrict__ B,
                                  const float* __restrict__ bias,
                                  float* __restrict__ C,
                                  int M, int N, int K) {
    const int BM = 128, BN = 64, BK = 16, TM = 8, TN = 4;
    __shared__ float As[BK][BM + 4];
    __shared__ float Bs[BK][BN];
    int tid = threadIdx.x;
    int bm = blockIdx.x * BM;
    int bn = blockIdx.y * BN;
    int ty = tid / (BN / TN);   // 0..15
    int tx = tid % (BN / TN);   // 0..15
    float acc[TM][TN];
#pragma unroll
    for (int i = 0; i < TM; i++)
#pragma unroll
        for (int j = 0; j < TN; j++) acc[i][j] = 0.f;

    int arow = tid / 4;               // 0..63
    int acol4 = (tid % 4) * 4;        // 0,4,8,12
    int brow = tid / 16;              // 0..15
    int bcol4 = (tid % 16) * 4;       // 0..60

    for (int k0 = 0; k0 < K; k0 += BK) {
#pragma unroll
        for (int p = 0; p < 2; p++) {
            int row = arow + p * 64;
            int gm = bm + row;
            float4 av = make_float4(0.f, 0.f, 0.f, 0.f);
            if (gm < M) av = *(const float4*)&A[(long)gm * K + k0 + acol4];
            As[acol4 + 0][row] = av.x;
            As[acol4 + 1][row] = av.y;
            As[acol4 + 2][row] = av.z;
            As[acol4 + 3][row] = av.w;
        }
        {
            float4 bv = *(const float4*)&B[(long)(k0 + brow) * N + bn + bcol4];
            *(float4*)&Bs[brow][bcol4] = bv;
        }
        __syncthreads();
#pragma unroll
        for (int kk = 0; kk < BK; kk++) {
            float a[TM], b[TN];
#pragma unroll
            for (int i = 0; i < TM; i++) a[i] = As[kk][ty * TM + i];
#pragma unroll
            for (int j = 0; j < TN; j++) b[j] = Bs[kk][tx * TN + j];
#pragma unroll
            for (int i = 0; i < TM; i++)
#pragma unroll
                for (int j = 0; j < TN; j++) acc[i][j] += a[i] * b[j];
        }
        __syncthreads();
    }
#pragma unroll
    for (int i = 0; i < TM; i++) {
        int gm = bm + ty * TM + i;
        if (gm >= M) continue;
#pragma unroll
        for (int j = 0; j < TN; j++) {
            int gn = bn + tx * TN + j;
            C[(long)gm * N + gn] = acc[i][j] + bias[gn];
        }
    }
}

// ---------------- attention: edge scores + segment max ----------------
template <int D>
__global__ void edge_scores_kernel(const float* __restrict__ q,
                                   const float* __restrict__ k,
                                   float scale) {
    int warp = (blockIdx.x * blockDim.x + threadIdx.x) >> 5;
    int lane = threadIdx.x & 31;
    int nwarp = (gridDim.x * blockDim.x) >> 5;
    for (int e = warp; e < N_EDGES; e += nwarp) {
        int s = g_src[e], d = g_dst[e];
        const float* qr = q + (long)d * D;
        const float* kr = k + (long)s * D;
        float acc = 0.f;
#pragma unroll
        for (int i = 0; i < D / 32; i++) acc += qr[lane + 32 * i] * kr[lane + 32 * i];
#pragma unroll
        for (int o = 16; o > 0; o >>= 1) acc += __shfl_xor_sync(0xffffffffu, acc, o);
        if (lane == 0) {
            float sc = acc * scale;
            g_score[e] = sc;
            unsigned key = __float_as_uint(sc);
            key = (key & 0x80000000u) ? ~key : (key | 0x80000000u);
            atomicMax(&g_mkey[d], key);
        }
    }
}

__global__ void edge_weights_kernel() {
    int stride = gridDim.x * blockDim.x;
    for (int e = blockIdx.x * blockDim.x + threadIdx.x; e < N_EDGES; e += stride) {
        int d = g_dst[e];
        unsigned key = g_mkey[d];
        unsigned bits = (key & 0x80000000u) ? (key ^ 0x80000000u) : ~key;
        float m = __uint_as_float(bits);
        float we = expf(g_score[e] - m);
        g_w[e] = we;
        atomicAdd(&g_denom[d], we);
    }
}

// out[n][c] = skip[n][c] + (1/denom[n]) * sum_e w[e] * v[src[e]][c]
template <int D>
__global__ void node_aggregate_kernel(const float* __restrict__ v,
                                      const float* __restrict__ skip,
                                      float* __restrict__ out) {
    int n = blockIdx.x;
    int c = threadIdx.x;
    int s0 = g_off[n], s1 = g_off[n + 1];
    float dn = g_denom[n];
    float inv = (s1 > s0 && dn > 0.f) ? 1.f / dn : 0.f;
    float acc = 0.f;
    for (int j = s0; j < s1; j++) {
        int e = g_csr[j];
        float we = g_w[e];
        int s = g_src[e];
        acc += we * v[(long)s * D + c];
    }
    out[(long)n * D + c] = skip[(long)n * D + c] + acc * inv;
}

// ---------------- graph layer norm ----------------
__global__ void reduce_stats_kernel(const float* __restrict__ h, long M) {
    double s = 0.0, s2 = 0.0;
    long stride = (long)gridDim.x * blockDim.x;
    for (long i = (long)blockIdx.x * blockDim.x + threadIdx.x; i < M; i += stride) {
        float xv = h[i];
        s += (double)xv;
        s2 += (double)xv * (double)xv;
    }
#pragma unroll
    for (int o = 16; o > 0; o >>= 1) {
        s += __shfl_xor_sync(0xffffffffu, s, o);
        s2 += __shfl_xor_sync(0xffffffffu, s2, o);
    }
    __shared__ double sh[2][8];
    int w = threadIdx.x >> 5, l = threadIdx.x & 31;
    if (l == 0) { sh[0][w] = s; sh[1][w] = s2; }
    __syncthreads();
    if (threadIdx.x == 0) {
        double ts = 0.0, ts2 = 0.0;
        int nw = blockDim.x >> 5;
        for (int i = 0; i < nw; i++) { ts += sh[0][i]; ts2 += sh[1][i]; }
        atomicAdd(&g_red[0], ts);
        atomicAdd(&g_red[1], ts2);
    }
}

template <bool ELU>
__global__ void normalize_kernel(const float* __restrict__ h,
                                 const float* __restrict__ gamma,
                                 const float* __restrict__ beta,
                                 float* __restrict__ out,
                                 int dmask, long M) {
    double mean = g_red[0] / (double)M;
    double var = g_red[1] / (double)M - mean * mean;
    if (var < 0.0) var = 0.0;
    float inv = 1.0f / ((float)sqrt(var) + 1e-5f);
    float fm = (float)mean;
    long stride = (long)gridDim.x * blockDim.x;
    for (long i = (long)blockIdx.x * blockDim.x + threadIdx.x; i < M; i += stride) {
        int c = (int)(i & dmask);
        float y = (h[i] - fm) * inv * gamma[c] + beta[c];
        if (ELU) y = (y > 0.f) ? y : expm1f(y);
        out[i] = y;
    }
}

// ---------------- host launcher ----------------
extern "C" void kernel_launch(void* const* d_in, const int* in_sizes, int n_in,
                              void* d_out, int out_size) {
    const float* x    = (const float*)d_in[0];
    const float* Wq1  = (const float*)d_in[1];
    const float* bq1  = (const float*)d_in[2];
    const float* Wk1  = (const float*)d_in[3];
    const float* bk1  = (const float*)d_in[4];
    const float* Wv1  = (const float*)d_in[5];
    const float* bv1  = (const float*)d_in[6];
    const float* Ws1  = (const float*)d_in[7];
    const float* bs1  = (const float*)d_in[8];
    const float* ga1  = (const float*)d_in[9];
    const float* be1  = (const float*)d_in[10];
    const float* Wq2  = (const float*)d_in[11];
    const float* bq2  = (const float*)d_in[12];
    const float* Wk2  = (const float*)d_in[13];
    const float* bk2  = (const float*)d_in[14];
    const float* Wv2  = (const float*)d_in[15];
    const float* bv2  = (const float*)d_in[16];
    const float* Ws2  = (const float*)d_in[17];
    const float* bs2  = (const float*)d_in[18];
    const float* ga2  = (const float*)d_in[19];
    const float* be2  = (const float*)d_in[20];
    const void*  ei   = d_in[21];
    float* out = (float*)d_out;

    void *p_q, *p_k, *p_v, *p_s, *p_h, *p_deg, *p_mkey, *p_denom, *p_red, *p_is64;
    cudaGetSymbolAddress(&p_q, g_q);
    cudaGetSymbolAddress(&p_k, g_k);
    cudaGetSymbolAddress(&p_v, g_v);
    cudaGetSymbolAddress(&p_s, g_s);
    cudaGetSymbolAddress(&p_h, g_h);
    cudaGetSymbolAddress(&p_deg, g_deg);
    cudaGetSymbolAddress(&p_mkey, g_mkey);
    cudaGetSymbolAddress(&p_denom, g_denom);
    cudaGetSymbolAddress(&p_red, g_red);
    cudaGetSymbolAddress(&p_is64, g_is64);

    float* q = (float*)p_q;
    float* k = (float*)p_k;
    float* v = (float*)p_v;
    float* s = (float*)p_s;
    float* h = (float*)p_h;

    // ---- edge dtype detection + CSR build (dst buckets) ----
    cudaMemsetAsync(p_is64, 0xFF, sizeof(int), 0);   // assume int64 until disproven
    // Only probe as int64 if the buffer could actually hold 2E int64 values.
    // in_sizes reports element count = 2E either way; int64 probe reads 2E*8 bytes.
    // If data is int32, buffer is 2E*4 bytes; reading 2E int64 would overrun by 2x.
    // So probe only the first E int64 slots (= full int32 buffer size), which is
    // enough: fused int32 pairs there already break validity.
    detect_idx_kernel<<<1024, 256>>>((const long long*)ei);
    cudaMemsetAsync(p_deg, 0, N_NODES * sizeof(int), 0);
    cvt_count_kernel<<<2048, 256>>>(ei);
    scan_offsets_kernel<<<1, 1024>>>();
    fill_csr_kernel<<<2048, 256>>>();

    // ---- layer 1 ----
    {
        dim3 grid((N_NODES + 127) / 128, HID / 64);
        sgemm_bias_kernel<<<grid, 256>>>(x, Wq1, bq1, q, N_NODES, HID, IN_DIM);
        sgemm_bias_kernel<<<grid, 256>>>(x, Wk1, bk1, k, N_NODES, HID, IN_DIM);
        sgemm_bias_kernel<<<grid, 256>>>(x, Wv1, bv1, v, N_NODES, HID, IN_DIM);
        sgemm_bias_kernel<<<grid, 256>>>(x, Ws1, bs1, s, N_NODES, HID, IN_DIM);
    }
    cudaMemsetAsync(p_mkey, 0, N_NODES * sizeof(unsigned), 0);
    cudaMemsetAsync(p_denom, 0, N_NODES * sizeof(float), 0);
    edge_scores_kernel<HID><<<2048, 256>>>(q, k, 1.0f / 16.0f);
    edge_weights_kernel<<<2048, 256>>>();
    node_aggregate_kernel<HID><<<N_NODES, HID>>>(v, s, h);

    cudaMemsetAsync(p_red, 0, 2 * sizeof(double), 0);
    reduce_stats_kernel<<<1024, 256>>>(h, (long)N_NODES * HID);
    normalize_kernel<true><<<2048, 256>>>(h, ga1, be1, h, HID - 1, (long)N_NODES * HID);

    // ---- layer 2 ----
    {
        dim3 grid((N_NODES + 127) / 128, OUT_DIM / 64);
        sgemm_bias_kernel<<<grid, 256>>>(h, Wq2, bq2, q, N_NODES, OUT_DIM, HID);
        sgemm_bias_kernel<<<grid, 256>>>(h, Wk2, bk2, k, N_NODES, OUT_DIM, HID);
        sgemm_bias_kernel<<<grid, 256>>>(h, Wv2, bv2, v, N_NODES, OUT_DIM, HID);
        sgemm_bias_kernel<<<grid, 256>>>(h, Ws2, bs2, s, N_NODES, OUT_DIM, HID);
    }
    cudaMemsetAsync(p_mkey, 0, N_NODES * sizeof(unsigned), 0);
    cudaMemsetAsync(p_denom, 0, N_NODES * sizeof(float), 0);
    edge_scores_kernel<OUT_DIM><<<2048, 256>>>(q, k, 0.08838834764831845f);
    edge_weights_kernel<<<2048, 256>>>();
    node_aggregate_kernel<OUT_DIM><<<N_NODES, OUT_DIM>>>(v, s, h);  // h1 no longer needed

    cudaMemsetAsync(p_red, 0, 2 * sizeof(double), 0);
    reduce_stats_kernel<<<1024, 256>>>(h, (long)N_NODES * OUT_DIM);
    normalize_kernel<false><<<2048, 256>>>(h, ga2, be2, out, OUT_DIM - 1, (long)N_NODES * OUT_DIM);
}

// round 4
// speedup vs baseline: 1.8369x; 1.8369x over previous
#include <cuda_runtime.h>
#include <cuda_bf16.h>
#include <math.h>

#define N_NODES 50000
#define N_EDGES 800000
#define IN_DIM  512
#define HID     256
#define OUT_DIM 128

// ---------------- scratch (static device globals; no allocation) ----------------
__device__ float    g_q[N_NODES * HID];
__device__ float    g_k[N_NODES * HID];
__device__ float    g_v[N_NODES * HID];
__device__ float    g_s[N_NODES * HID];   // skip (x@Ws+bs)
__device__ float    g_h[N_NODES * HID];   // conv out -> h1 -> conv2 out
__device__ float    g_score[N_EDGES];
__device__ float    g_w[N_EDGES];
__device__ unsigned g_mkey[N_NODES];
__device__ float    g_denom[N_NODES];
__device__ int      g_deg[N_NODES];
__device__ int      g_off[N_NODES + 1];
__device__ int      g_cursor[N_NODES];
__device__ int      g_csr[N_EDGES];
__device__ int      g_src[N_EDGES];
__device__ int      g_dst[N_EDGES];
__device__ double   g_red[2];
__device__ int      g_is64;

// ---------------- edge-index dtype detection ----------------
// Probe only the first N_EDGES int64 slots (covers the whole buffer even if it
// is int32). If values fuse int32 pairs, some slot lands outside [0, N).
__global__ void detect_idx_kernel(const long long* __restrict__ ei) {
    int stride = gridDim.x * blockDim.x;
    int bad = 0;
    for (int i = blockIdx.x * blockDim.x + threadIdx.x; i < N_EDGES; i += stride) {
        long long v = ei[i];
        if (v < 0 || v >= N_NODES) bad = 1;
    }
    if (__syncthreads_or(bad) && threadIdx.x == 0) atomicAnd(&g_is64, 0);
}

// ---------------- edge preprocessing ----------------
__global__ void cvt_count_kernel(const void* __restrict__ eiv) {
    const bool is64 = (g_is64 != 0);
    const long long* e64 = (const long long*)eiv;
    const int*       e32 = (const int*)eiv;
    int stride = gridDim.x * blockDim.x;
    for (int e = blockIdx.x * blockDim.x + threadIdx.x; e < N_EDGES; e += stride) {
        long long sv = is64 ? e64[e]           : (long long)e32[e];
        long long dv = is64 ? e64[N_EDGES + e] : (long long)e32[N_EDGES + e];
        int s = (int)sv, d = (int)dv;
        if (s < 0) s = 0; if (s >= N_NODES) s = N_NODES - 1;
        if (d < 0) d = 0; if (d >= N_NODES) d = N_NODES - 1;
        g_src[e] = s;
        g_dst[e] = d;
        atomicAdd(&g_deg[d], 1);
    }
}

__global__ void scan_offsets_kernel() {
    __shared__ int partial[1024];
    int t = threadIdx.x;
    const int C = (N_NODES + 1023) / 1024;
    int lo = t * C;
    int hi = lo + C; if (hi > N_NODES) hi = N_NODES;
    if (lo > N_NODES) lo = N_NODES;
    int s = 0;
    for (int i = lo; i < hi; i++) s += g_deg[i];
    partial[t] = s;
    __syncthreads();
    for (int o = 1; o < 1024; o <<= 1) {
        int add = (t >= o) ? partial[t - o] : 0;
        __syncthreads();
        partial[t] += add;
        __syncthreads();
    }
    int run = partial[t] - s;
    for (int i = lo; i < hi; i++) {
        g_off[i] = run;
        g_cursor[i] = run;
        run += g_deg[i];
    }
    if (t == 1023) g_off[N_NODES] = partial[1023];
}

__global__ void fill_csr_kernel() {
    int stride = gridDim.x * blockDim.x;
    for (int e = blockIdx.x * blockDim.x + threadIdx.x; e < N_EDGES; e += stride) {
        int p = atomicAdd(&g_cursor[g_dst[e]], 1);
        if (p >= 0 && p < N_EDGES) g_csr[p] = e;
    }
}

// ---------------- TF32 tensor-core GEMM ----------------
// C = A[MxK] @ B[KxN] + bias; 4 (B,bias,C) sets selected by blockIdx.z.
// Block tile 128x128, 8 warps in 2x4 grid, warp tile 64x32 via m16n8k8.
// cp.async double-buffered shared tiles, BK=16.

__device__ __forceinline__ unsigned f2tf(float x) {
    unsigned r;
    asm("cvt.rna.tf32.f32 %0, %1;" : "=r"(r) : "f"(x));
    return r;
}

__device__ __forceinline__ void mma_tf32(float* c, const unsigned* a, const unsigned* b) {
    asm volatile(
        "mma.sync.aligned.m16n8k8.row.col.f32.tf32.tf32.f32 "
        "{%0,%1,%2,%3}, {%4,%5,%6,%7}, {%8,%9}, {%0,%1,%2,%3};"
        : "+f"(c[0]), "+f"(c[1]), "+f"(c[2]), "+f"(c[3])
        : "r"(a[0]), "r"(a[1]), "r"(a[2]), "r"(a[3]), "r"(b[0]), "r"(b[1]));
}

__device__ __forceinline__ void cpasync16(void* smem, const void* gmem) {
    unsigned saddr = (unsigned)__cvta_generic_to_shared(smem);
    asm volatile("cp.async.ca.shared.global [%0], [%1], 16;" :: "r"(saddr), "l"(gmem));
}

#define APAD 20   // floats per As row (16 + 4 pad); 80B, 16B-aligned
#define BPAD 132  // floats per Bs row (128 + 4 pad); 528B, 16B-aligned

__global__ void __launch_bounds__(256, 2)
gemm4_tf32_kernel(const float* __restrict__ A,
                  const float* __restrict__ B0, const float* __restrict__ B1,
                  const float* __restrict__ B2, const float* __restrict__ B3,
                  const float* __restrict__ c0, const float* __restrict__ c1,
                  const float* __restrict__ c2, const float* __restrict__ c3,
                  float* __restrict__ O0, float* __restrict__ O1,
                  float* __restrict__ O2, float* __restrict__ O3,
                  int M, int N, int K) {
    const float* B; const float* bias; float* O;
    switch (blockIdx.z) {
        case 0: B = B0; bias = c0; O = O0; break;
        case 1: B = B1; bias = c1; O = O1; break;
        case 2: B = B2; bias = c2; O = O2; break;
        default: B = B3; bias = c3; O = O3; break;
    }

    __shared__ float As[2][128][APAD];
    __shared__ float Bs[2][16][BPAD];

    int tid = threadIdx.x;
    int lane = tid & 31;
    int wid = tid >> 5;
    int wr = wid >> 2;          // 0..1
    int wc = wid & 3;           // 0..3
    int grp = lane >> 2;        // 0..7
    int qid = lane & 3;         // 0..3
    int bm = blockIdx.x * 128;
    int bn = blockIdx.y * 128;

    float acc[4][4][4];
#pragma unroll
    for (int i = 0; i < 4; i++)
#pragma unroll
        for (int j = 0; j < 4; j++)
#pragma unroll
            for (int r = 0; r < 4; r++) acc[i][j][r] = 0.f;

    // load-index precompute
    // A tile: 128 rows x 16 cols = 512 float4; 2 per thread
    int a_idx0 = tid, a_idx1 = tid + 256;
    int a_row0 = a_idx0 >> 2, a_c40 = (a_idx0 & 3) * 4;
    int a_row1 = a_idx1 >> 2, a_c41 = (a_idx1 & 3) * 4;
    int a_gr0 = bm + a_row0; if (a_gr0 >= M) a_gr0 = M - 1;  // clamp; masked at store
    int a_gr1 = bm + a_row1; if (a_gr1 >= M) a_gr1 = M - 1;
    // B tile: 16 rows x 128 cols = 512 float4; 2 per thread
    int b_idx0 = tid, b_idx1 = tid + 256;
    int b_row0 = b_idx0 >> 5, b_c40 = (b_idx0 & 31) * 4;
    int b_row1 = b_idx1 >> 5, b_c41 = (b_idx1 & 31) * 4;

    int KT = K / 16;

    // prefetch tile 0
    {
        int k0 = 0;
        cpasync16(&As[0][a_row0][a_c40], &A[(long)a_gr0 * K + k0 + a_c40]);
        cpasync16(&As[0][a_row1][a_c41], &A[(long)a_gr1 * K + k0 + a_c41]);
        cpasync16(&Bs[0][b_row0][b_c40], &B[(long)(k0 + b_row0) * N + bn + b_c40]);
        cpasync16(&Bs[0][b_row1][b_c41], &B[(long)(k0 + b_row1) * N + bn + b_c41]);
        asm volatile("cp.async.commit_group;");
    }

    for (int kt = 0; kt < KT; kt++) {
        int buf = kt & 1;
        if (kt + 1 < KT) {
            int k0 = (kt + 1) * 16;
            int nb = (kt + 1) & 1;
            cpasync16(&As[nb][a_row0][a_c40], &A[(long)a_gr0 * K + k0 + a_c40]);
            cpasync16(&As[nb][a_row1][a_c41], &A[(long)a_gr1 * K + k0 + a_c41]);
            cpasync16(&Bs[nb][b_row0][b_c40], &B[(long)(k0 + b_row0) * N + bn + b_c40]);
            cpasync16(&Bs[nb][b_row1][b_c41], &B[(long)(k0 + b_row1) * N + bn + b_c41]);
            asm volatile("cp.async.commit_group;");
            asm volatile("cp.async.wait_group 1;");
        } else {
            asm volatile("cp.async.wait_group 0;");
        }
        __syncthreads();

#pragma unroll
        for (int ks = 0; ks < 16; ks += 8) {
            unsigned afr[4][4];
#pragma unroll
            for (int mi = 0; mi < 4; mi++) {
                int r0 = wr * 64 + mi * 16 + grp;
                afr[mi][0] = f2tf(As[buf][r0][ks + qid]);
                afr[mi][1] = f2tf(As[buf][r0 + 8][ks + qid]);
                afr[mi][2] = f2tf(As[buf][r0][ks + qid + 4]);
                afr[mi][3] = f2tf(As[buf][r0 + 8][ks + qid + 4]);
            }
            unsigned bfr[4][2];
#pragma unroll
            for (int ni = 0; ni < 4; ni++) {
                int col = wc * 32 + ni * 8 + grp;
                bfr[ni][0] = f2tf(Bs[buf][ks + qid][col]);
                bfr[ni][1] = f2tf(Bs[buf][ks + qid + 4][col]);
            }
#pragma unroll
            for (int mi = 0; mi < 4; mi++)
#pragma unroll
                for (int ni = 0; ni < 4; ni++)
                    mma_tf32(acc[mi][ni], afr[mi], bfr[ni]);
        }
        __syncthreads();
    }

    // epilogue
#pragma unroll
    for (int mi = 0; mi < 4; mi++) {
        int r0 = bm + wr * 64 + mi * 16 + grp;
#pragma unroll
        for (int ni = 0; ni < 4; ni++) {
            int gc = bn + wc * 32 + ni * 8 + 2 * qid;
            float bz0 = bias[gc], bz1 = bias[gc + 1];
            if (r0 < M) {
                O[(long)r0 * N + gc]     = acc[mi][ni][0] + bz0;
                O[(long)r0 * N + gc + 1] = acc[mi][ni][1] + bz1;
            }
            if (r0 + 8 < M) {
                O[(long)(r0 + 8) * N + gc]     = acc[mi][ni][2] + bz0;
                O[(long)(r0 + 8) * N + gc + 1] = acc[mi][ni][3] + bz1;
            }
        }
    }
}

// ---------------- attention: edge scores + segment max ----------------
template <int D>
__global__ void edge_scores_kernel(const float* __restrict__ q,
                                   const float* __restrict__ k,
                                   float scale) {
    int warp = (blockIdx.x * blockDim.x + threadIdx.x) >> 5;
    int lane = threadIdx.x & 31;
    int nwarp = (gridDim.x * blockDim.x) >> 5;
    for (int e = warp; e < N_EDGES; e += nwarp) {
        int s = g_src[e], d = g_dst[e];
        const float4* qr = (const float4*)(q + (long)d * D);
        const float4* kr = (const float4*)(k + (long)s * D);
        float acc = 0.f;
#pragma unroll
        for (int i = 0; i < D / 128; i++) {
            float4 a = qr[lane + 32 * i];
            float4 b = kr[lane + 32 * i];
            acc += a.x * b.x + a.y * b.y + a.z * b.z + a.w * b.w;
        }
#pragma unroll
        for (int o = 16; o > 0; o >>= 1) acc += __shfl_xor_sync(0xffffffffu, acc, o);
        if (lane == 0) {
            float sc = acc * scale;
            g_score[e] = sc;
            unsigned key = __float_as_uint(sc);
            key = (key & 0x80000000u) ? ~key : (key | 0x80000000u);
            atomicMax(&g_mkey[d], key);
        }
    }
}

__global__ void edge_weights_kernel() {
    int stride = gridDim.x * blockDim.x;
    for (int e = blockIdx.x * blockDim.x + threadIdx.x; e < N_EDGES; e += stride) {
        int d = g_dst[e];
        unsigned key = g_mkey[d];
        unsigned bits = (key & 0x80000000u) ? (key ^ 0x80000000u) : ~key;
        float m = __uint_as_float(bits);
        float we = expf(g_score[e] - m);
        g_w[e] = we;
        atomicAdd(&g_denom[d], we);
    }
}

// out[n][c] = skip[n][c] + (1/denom[n]) * sum_e w[e] * v[src[e]][c]
template <int D>
__global__ void node_aggregate_kernel(const float* __restrict__ v,
                                      const float* __restrict__ skip,
                                      float* __restrict__ out) {
    int n = blockIdx.x;
    int c = threadIdx.x;
    int s0 = g_off[n], s1 = g_off[n + 1];
    float dn = g_denom[n];
    float inv = (s1 > s0 && dn > 0.f) ? 1.f / dn : 0.f;
    float acc = 0.f;
    for (int j = s0; j < s1; j++) {
        int e = g_csr[j];
        float we = g_w[e];
        int s = g_src[e];
        acc += we * v[(long)s * D + c];
    }
    out[(long)n * D + c] = skip[(long)n * D + c] + acc * inv;
}

// ---------------- graph layer norm ----------------
__global__ void reduce_stats_kernel(const float* __restrict__ h, long M) {
    double s = 0.0, s2 = 0.0;
    long stride = (long)gridDim.x * blockDim.x;
    for (long i = (long)blockIdx.x * blockDim.x + threadIdx.x; i < M; i += stride) {
        float xv = h[i];
        s += (double)xv;
        s2 += (double)xv * (double)xv;
    }
#pragma unroll
    for (int o = 16; o > 0; o >>= 1) {
        s += __shfl_xor_sync(0xffffffffu, s, o);
        s2 += __shfl_xor_sync(0xffffffffu, s2, o);
    }
    __shared__ double sh[2][8];
    int w = threadIdx.x >> 5, l = threadIdx.x & 31;
    if (l == 0) { sh[0][w] = s; sh[1][w] = s2; }
    __syncthreads();
    if (threadIdx.x == 0) {
        double ts = 0.0, ts2 = 0.0;
        int nw = blockDim.x >> 5;
        for (int i = 0; i < nw; i++) { ts += sh[0][i]; ts2 += sh[1][i]; }
        atomicAdd(&g_red[0], ts);
        atomicAdd(&g_red[1], ts2);
    }
}

template <bool ELU>
__global__ void normalize_kernel(const float* __restrict__ h,
                                 const float* __restrict__ gamma,
                                 const float* __restrict__ beta,
                                 float* __restrict__ out,
                                 int dmask, long M) {
    double mean = g_red[0] / (double)M;
    double var = g_red[1] / (double)M - mean * mean;
    if (var < 0.0) var = 0.0;
    float inv = 1.0f / ((float)sqrt(var) + 1e-5f);
    float fm = (float)mean;
    long stride = (long)gridDim.x * blockDim.x;
    for (long i = (long)blockIdx.x * blockDim.x + threadIdx.x; i < M; i += stride) {
        int c = (int)(i & dmask);
        float y = (h[i] - fm) * inv * gamma[c] + beta[c];
        if (ELU) y = (y > 0.f) ? y : expm1f(y);
        out[i] = y;
    }
}

// ---------------- host launcher ----------------
extern "C" void kernel_launch(void* const* d_in, const int* in_sizes, int n_in,
                              void* d_out, int out_size) {
    const float* x    = (const float*)d_in[0];
    const float* Wq1  = (const float*)d_in[1];
    const float* bq1  = (const float*)d_in[2];
    const float* Wk1  = (const float*)d_in[3];
    const float* bk1  = (const float*)d_in[4];
    const float* Wv1  = (const float*)d_in[5];
    const float* bv1  = (const float*)d_in[6];
    const float* Ws1  = (const float*)d_in[7];
    const float* bs1  = (const float*)d_in[8];
    const float* ga1  = (const float*)d_in[9];
    const float* be1  = (const float*)d_in[10];
    const float* Wq2  = (const float*)d_in[11];
    const float* bq2  = (const float*)d_in[12];
    const float* Wk2  = (const float*)d_in[13];
    const float* bk2  = (const float*)d_in[14];
    const float* Wv2  = (const float*)d_in[15];
    const float* bv2  = (const float*)d_in[16];
    const float* Ws2  = (const float*)d_in[17];
    const float* bs2  = (const float*)d_in[18];
    const float* ga2  = (const float*)d_in[19];
    const float* be2  = (const float*)d_in[20];
    const void*  ei   = d_in[21];
    float* out = (float*)d_out;

    void *p_q, *p_k, *p_v, *p_s, *p_h, *p_deg, *p_mkey, *p_denom, *p_red, *p_is64;
    cudaGetSymbolAddress(&p_q, g_q);
    cudaGetSymbolAddress(&p_k, g_k);
    cudaGetSymbolAddress(&p_v, g_v);
    cudaGetSymbolAddress(&p_s, g_s);
    cudaGetSymbolAddress(&p_h, g_h);
    cudaGetSymbolAddress(&p_deg, g_deg);
    cudaGetSymbolAddress(&p_mkey, g_mkey);
    cudaGetSymbolAddress(&p_denom, g_denom);
    cudaGetSymbolAddress(&p_red, g_red);
    cudaGetSymbolAddress(&p_is64, g_is64);

    float* q = (float*)p_q;
    float* k = (float*)p_k;
    float* v = (float*)p_v;
    float* s = (float*)p_s;
    float* h = (float*)p_h;

    // ---- edge dtype detection + CSR build ----
    cudaMemsetAsync(p_is64, 0xFF, sizeof(int), 0);
    detect_idx_kernel<<<1024, 256>>>((const long long*)ei);
    cudaMemsetAsync(p_deg, 0, N_NODES * sizeof(int), 0);
    cvt_count_kernel<<<2048, 256>>>(ei);
    scan_offsets_kernel<<<1, 1024>>>();
    fill_csr_kernel<<<2048, 256>>>();

    // ---- layer 1: fused 4x GEMM (tf32 tensor cores) ----
    {
        dim3 grid((N_NODES + 127) / 128, HID / 128, 4);
        gemm4_tf32_kernel<<<grid, 256>>>(x, Wq1, Wk1, Wv1, Ws1,
                                         bq1, bk1, bv1, bs1,
                                         q, k, v, s, N_NODES, HID, IN_DIM);
    }
    cudaMemsetAsync(p_mkey, 0, N_NODES * sizeof(unsigned), 0);
    cudaMemsetAsync(p_denom, 0, N_NODES * sizeof(float), 0);
    edge_scores_kernel<HID><<<2048, 256>>>(q, k, 1.0f / 16.0f);
    edge_weights_kernel<<<2048, 256>>>();
    node_aggregate_kernel<HID><<<N_NODES, HID>>>(v, s, h);

    cudaMemsetAsync(p_red, 0, 2 * sizeof(double), 0);
    reduce_stats_kernel<<<1024, 256>>>(h, (long)N_NODES * HID);
    normalize_kernel<true><<<2048, 256>>>(h, ga1, be1, h, HID - 1, (long)N_NODES * HID);

    // ---- layer 2: fused 4x GEMM ----
    {
        dim3 grid((N_NODES + 127) / 128, OUT_DIM / 128, 4);
        gemm4_tf32_kernel<<<grid, 256>>>(h, Wq2, Wk2, Wv2, Ws2,
                                         bq2, bk2, bv2, bs2,
                                         q, k, v, s, N_NODES, OUT_DIM, HID);
    }
    cudaMemsetAsync(p_mkey, 0, N_NODES * sizeof(unsigned), 0);
    cudaMemsetAsync(p_denom, 0, N_NODES * sizeof(float), 0);
    edge_scores_kernel<OUT_DIM><<<2048, 256>>>(q, k, 0.08838834764831845f);
    edge_weights_kernel<<<2048, 256>>>();
    node_aggregate_kernel<OUT_DIM><<<N_NODES, OUT_DIM>>>(v, s, h);

    cudaMemsetAsync(p_red, 0, 2 * sizeof(double), 0);
    reduce_stats_kernel<<<1024, 256>>>(h, (long)N_NODES * OUT_DIM);
    normalize_kernel<false><<<2048, 256>>>(h, ga2, be2, out, OUT_DIM - 1, (long)N_NODES * OUT_DIM);
}

// round 5
// speedup vs baseline: 1.9706x; 1.0728x over previous
#include <cuda_runtime.h>
#include <cuda_bf16.h>
#include <math.h>

#define N_NODES 50000
#define N_EDGES 800000
#define IN_DIM  512
#define HID     256
#define OUT_DIM 128

// ---------------- scratch (static device globals; no allocation) ----------------
__device__ float    g_q[N_NODES * HID];
__device__ float    g_k[N_NODES * HID];
__device__ float    g_v[N_NODES * HID];
__device__ float    g_s[N_NODES * HID];      // skip (x@Ws+bs)
__device__ float    g_h[N_NODES * HID];      // conv out (pre-LN)
__device__ float    g_xc[N_NODES * IN_DIM];  // tf32-preconverted GEMM A operand
__device__ float    g_wc[4 * IN_DIM * HID];  // tf32-preconverted weights (4 mats)
__device__ float    g_w[N_EDGES];            // CSR-slot-ordered scores -> softmax w
__device__ float    g_dinv[N_NODES];         // 1/denom per node
__device__ int      g_deg[N_NODES];
__device__ int      g_off[N_NODES + 1];
__device__ int      g_cursor[N_NODES];
__device__ int      g_csrsrc[N_EDGES];       // src node per CSR slot
__device__ int      g_src[N_EDGES];
__device__ int      g_dst[N_EDGES];
__device__ double   g_red[2];
__device__ int      g_is64;

__device__ __forceinline__ unsigned f2tf(float x) {
    unsigned r;
    asm("cvt.rna.tf32.f32 %0, %1;" : "=r"(r) : "f"(x));
    return r;
}

// ---------------- edge-index dtype detection ----------------
__global__ void detect_idx_kernel(const long long* __restrict__ ei) {
    int stride = gridDim.x * blockDim.x;
    int bad = 0;
    for (int i = blockIdx.x * blockDim.x + threadIdx.x; i < N_EDGES; i += stride) {
        long long v = ei[i];
        if (v < 0 || v >= N_NODES) bad = 1;
    }
    if (__syncthreads_or(bad) && threadIdx.x == 0) atomicAnd(&g_is64, 0);
}

// ---------------- edge preprocessing ----------------
__global__ void cvt_count_kernel(const void* __restrict__ eiv) {
    const bool is64 = (g_is64 != 0);
    const long long* e64 = (const long long*)eiv;
    const int*       e32 = (const int*)eiv;
    int stride = gridDim.x * blockDim.x;
    for (int e = blockIdx.x * blockDim.x + threadIdx.x; e < N_EDGES; e += stride) {
        long long sv = is64 ? e64[e]           : (long long)e32[e];
        long long dv = is64 ? e64[N_EDGES + e] : (long long)e32[N_EDGES + e];
        int s = (int)sv, d = (int)dv;
        if (s < 0) s = 0; if (s >= N_NODES) s = N_NODES - 1;
        if (d < 0) d = 0; if (d >= N_NODES) d = N_NODES - 1;
        g_src[e] = s;
        g_dst[e] = d;
        atomicAdd(&g_deg[d], 1);
    }
}

__global__ void scan_offsets_kernel() {
    __shared__ int partial[1024];
    int t = threadIdx.x;
    const int C = (N_NODES + 1023) / 1024;
    int lo = t * C;
    int hi = lo + C; if (hi > N_NODES) hi = N_NODES;
    if (lo > N_NODES) lo = N_NODES;
    int s = 0;
    for (int i = lo; i < hi; i++) s += g_deg[i];
    partial[t] = s;
    __syncthreads();
    for (int o = 1; o < 1024; o <<= 1) {
        int add = (t >= o) ? partial[t - o] : 0;
        __syncthreads();
        partial[t] += add;
        __syncthreads();
    }
    int run = partial[t] - s;
    for (int i = lo; i < hi; i++) {
        g_off[i] = run;
        g_cursor[i] = run;
        run += g_deg[i];
    }
    if (t == 1023) g_off[N_NODES] = partial[1023];
}

__global__ void fill_csr_kernel() {
    int stride = gridDim.x * blockDim.x;
    for (int e = blockIdx.x * blockDim.x + threadIdx.x; e < N_EDGES; e += stride) {
        int p = atomicAdd(&g_cursor[g_dst[e]], 1);
        if (p >= 0 && p < N_EDGES) g_csrsrc[p] = g_src[e];
    }
}

// ---------------- tf32 pre-conversion ----------------
__global__ void cvt_tf32_kernel(const float* __restrict__ in, float* __restrict__ out, int n) {
    int stride = gridDim.x * blockDim.x;
    for (int i = blockIdx.x * blockDim.x + threadIdx.x; i < n; i += stride)
        out[i] = __uint_as_float(f2tf(in[i]));
}

// ---------------- TF32 tensor-core GEMM ----------------
// C = A[MxK] @ B[KxN] + bias; 4 (B,bias,C) sets via blockIdx.z.
// Inputs are PRE-CONVERTED to tf32 grid (pass raw bits to MMA).
// Block tile 128x128, 8 warps (2x4), warp tile 64x32 via m16n8k8.
// 4-stage cp.async pipeline, dynamic smem.

__device__ __forceinline__ void mma_tf32(float* c, const unsigned* a, const unsigned* b) {
    asm volatile(
        "mma.sync.aligned.m16n8k8.row.col.f32.tf32.tf32.f32 "
        "{%0,%1,%2,%3}, {%4,%5,%6,%7}, {%8,%9}, {%0,%1,%2,%3};"
        : "+f"(c[0]), "+f"(c[1]), "+f"(c[2]), "+f"(c[3])
        : "r"(a[0]), "r"(a[1]), "r"(a[2]), "r"(a[3]), "r"(b[0]), "r"(b[1]));
}

__device__ __forceinline__ void cpasync16(void* smem, const void* gmem) {
    unsigned saddr = (unsigned)__cvta_generic_to_shared(smem);
    asm volatile("cp.async.ca.shared.global [%0], [%1], 16;" :: "r"(saddr), "l"(gmem));
}

#define APAD 20   // floats per As row
#define BPAD 136  // floats per Bs row (conflict-free: bank = 8*qid + grp)
#define GSTAGES 4
#define GEMM_SMEM_BYTES ((GSTAGES * 128 * APAD + GSTAGES * 16 * BPAD) * 4)

__global__ void __launch_bounds__(256, 2)
gemm4_tf32_kernel(const float* __restrict__ A,
                  const float* __restrict__ B0, const float* __restrict__ B1,
                  const float* __restrict__ B2, const float* __restrict__ B3,
                  const float* __restrict__ c0, const float* __restrict__ c1,
                  const float* __restrict__ c2, const float* __restrict__ c3,
                  float* __restrict__ O0, float* __restrict__ O1,
                  float* __restrict__ O2, float* __restrict__ O3,
                  int M, int N, int K) {
    const float* B; const float* bias; float* O;
    switch (blockIdx.z) {
        case 0: B = B0; bias = c0; O = O0; break;
        case 1: B = B1; bias = c1; O = O1; break;
        case 2: B = B2; bias = c2; O = O2; break;
        default: B = B3; bias = c3; O = O3; break;
    }

    extern __shared__ float dsm[];
    float (*As)[128][APAD] = (float(*)[128][APAD])dsm;
    float (*Bs)[16][BPAD]  = (float(*)[16][BPAD])(dsm + GSTAGES * 128 * APAD);

    int tid = threadIdx.x;
    int lane = tid & 31;
    int wid = tid >> 5;
    int wr = wid >> 2;
    int wc = wid & 3;
    int grp = lane >> 2;
    int qid = lane & 3;
    int bm = blockIdx.x * 128;
    int bn = blockIdx.y * 128;

    float acc[4][4][4];
#pragma unroll
    for (int i = 0; i < 4; i++)
#pragma unroll
        for (int j = 0; j < 4; j++)
#pragma unroll
            for (int r = 0; r < 4; r++) acc[i][j][r] = 0.f;

    int a_row0 = tid >> 2,          a_c40 = (tid & 3) * 4;
    int a_row1 = (tid + 256) >> 2,  a_c41 = (tid & 3) * 4;
    int a_gr0 = bm + a_row0; if (a_gr0 >= M) a_gr0 = M - 1;
    int a_gr1 = bm + a_row1; if (a_gr1 >= M) a_gr1 = M - 1;
    int b_row0 = tid >> 5,          b_c40 = (tid & 31) * 4;
    int b_row1 = (tid + 256) >> 5,  b_c41 = (tid & 31) * 4;

    int KT = K / 16;

#define PREFETCH(st, kt_) do { \
        int k0_ = (kt_) * 16; \
        cpasync16(&As[st][a_row0][a_c40], &A[(long)a_gr0 * K + k0_ + a_c40]); \
        cpasync16(&As[st][a_row1][a_c41], &A[(long)a_gr1 * K + k0_ + a_c41]); \
        cpasync16(&Bs[st][b_row0][b_c40], &B[(long)(k0_ + b_row0) * N + bn + b_c40]); \
        cpasync16(&Bs[st][b_row1][b_c41], &B[(long)(k0_ + b_row1) * N + bn + b_c41]); \
        asm volatile("cp.async.commit_group;"); \
    } while (0)

    for (int st = 0; st < 3 && st < KT; st++) PREFETCH(st, st);

    for (int kt = 0; kt < KT; kt++) {
        int rem = KT - 1 - kt;
        if (rem >= 2)      asm volatile("cp.async.wait_group 2;");
        else if (rem == 1) asm volatile("cp.async.wait_group 1;");
        else               asm volatile("cp.async.wait_group 0;");
        __syncthreads();
        if (kt + 3 < KT) PREFETCH((kt + 3) & 3, kt + 3);
        int buf = kt & 3;

#pragma unroll
        for (int ks = 0; ks < 16; ks += 8) {
            unsigned afr[4][4];
#pragma unroll
            for (int mi = 0; mi < 4; mi++) {
                int r0 = wr * 64 + mi * 16 + grp;
                afr[mi][0] = __float_as_uint(As[buf][r0][ks + qid]);
                afr[mi][1] = __float_as_uint(As[buf][r0 + 8][ks + qid]);
                afr[mi][2] = __float_as_uint(As[buf][r0][ks + qid + 4]);
                afr[mi][3] = __float_as_uint(As[buf][r0 + 8][ks + qid + 4]);
            }
            unsigned bfr[4][2];
#pragma unroll
            for (int ni = 0; ni < 4; ni++) {
                int col = wc * 32 + ni * 8 + grp;
                bfr[ni][0] = __float_as_uint(Bs[buf][ks + qid][col]);
                bfr[ni][1] = __float_as_uint(Bs[buf][ks + qid + 4][col]);
            }
#pragma unroll
            for (int mi = 0; mi < 4; mi++)
#pragma unroll
                for (int ni = 0; ni < 4; ni++)
                    mma_tf32(acc[mi][ni], afr[mi], bfr[ni]);
        }
        __syncthreads();
    }
#undef PREFETCH

#pragma unroll
    for (int mi = 0; mi < 4; mi++) {
        int r0 = bm + wr * 64 + mi * 16 + grp;
#pragma unroll
        for (int ni = 0; ni < 4; ni++) {
            int gc = bn + wc * 32 + ni * 8 + 2 * qid;
            float bz0 = bias[gc], bz1 = bias[gc + 1];
            if (r0 < M) {
                O[(long)r0 * N + gc]     = acc[mi][ni][0] + bz0;
                O[(long)r0 * N + gc + 1] = acc[mi][ni][1] + bz1;
            }
            if (r0 + 8 < M) {
                O[(long)(r0 + 8) * N + gc]     = acc[mi][ni][2] + bz0;
                O[(long)(r0 + 8) * N + gc + 1] = acc[mi][ni][3] + bz1;
            }
        }
    }
}

// ---------------- fused per-node scores + softmax (no atomics) ----------------
template <int D, int WARPS>
__global__ void __launch_bounds__(WARPS * 32)
score_softmax_kernel(const float* __restrict__ q,
                     const float* __restrict__ k,
                     float scale) {
    int n = blockIdx.x;
    __shared__ float qs[D];
    __shared__ float red[WARPS];
    __shared__ float bcast;
    int tid = threadIdx.x, lane = tid & 31, wid = tid >> 5;
    int s0 = g_off[n], s1 = g_off[n + 1];

    for (int i = tid; i < D; i += WARPS * 32) qs[i] = q[(long)n * D + i];
    __syncthreads();

    float lmax = -3.4e38f;
    const float4* qr = (const float4*)qs;
    for (int j = s0 + wid; j < s1; j += WARPS) {
        int src = g_csrsrc[j];
        const float4* kr = (const float4*)(k + (long)src * D);
        float acc = 0.f;
#pragma unroll
        for (int i = 0; i < D / 128; i++) {
            float4 a = qr[lane + 32 * i];
            float4 b = kr[lane + 32 * i];
            acc += a.x * b.x + a.y * b.y + a.z * b.z + a.w * b.w;
        }
#pragma unroll
        for (int o = 16; o > 0; o >>= 1) acc += __shfl_xor_sync(0xffffffffu, acc, o);
        float sc = acc * scale;
        if (lane == 0) g_w[j] = sc;
        lmax = fmaxf(lmax, sc);
    }
    if (lane == 0) red[wid] = lmax;
    __syncthreads();
    if (tid == 0) {
        float m = red[0];
#pragma unroll
        for (int i = 1; i < WARPS; i++) m = fmaxf(m, red[i]);
        bcast = m;
    }
    __syncthreads();
    float m = bcast;

    float lsum = 0.f;
    for (int j = s0 + tid; j < s1; j += WARPS * 32) {
        float w = __expf(g_w[j] - m);
        g_w[j] = w;
        lsum += w;
    }
#pragma unroll
    for (int o = 16; o > 0; o >>= 1) lsum += __shfl_xor_sync(0xffffffffu, lsum, o);
    if (lane == 0) red[wid] = lsum;
    __syncthreads();
    if (tid == 0) {
        float sum = 0.f;
#pragma unroll
        for (int i = 0; i < WARPS; i++) sum += red[i];
        g_dinv[n] = (sum > 0.f) ? 1.f / sum : 0.f;
    }
}

// out[n][c] = skip[n][c] + dinv[n] * sum_j w[j] * v[src[j]][c]
template <int D>
__global__ void node_aggregate_kernel(const float* __restrict__ v,
                                      const float* __restrict__ skip,
                                      float* __restrict__ out) {
    int n = blockIdx.x;
    int c = threadIdx.x;
    int s0 = g_off[n], s1 = g_off[n + 1];
    float inv = g_dinv[n];
    float acc0 = 0.f, acc1 = 0.f;
    int j = s0;
    for (; j + 1 < s1; j += 2) {
        int sa = g_csrsrc[j], sb = g_csrsrc[j + 1];
        float wa = g_w[j], wb = g_w[j + 1];
        acc0 += wa * v[(long)sa * D + c];
        acc1 += wb * v[(long)sb * D + c];
    }
    if (j < s1) acc0 += g_w[j] * v[(long)g_csrsrc[j] * D + c];
    out[(long)n * D + c] = skip[(long)n * D + c] + (acc0 + acc1) * inv;
}

// ---------------- graph layer norm ----------------
__global__ void reduce_stats_kernel(const float* __restrict__ h, long M) {
    double s = 0.0, s2 = 0.0;
    long stride = (long)gridDim.x * blockDim.x;
    for (long i = (long)blockIdx.x * blockDim.x + threadIdx.x; i < M; i += stride) {
        float xv = h[i];
        s += (double)xv;
        s2 += (double)xv * (double)xv;
    }
#pragma unroll
    for (int o = 16; o > 0; o >>= 1) {
        s += __shfl_xor_sync(0xffffffffu, s, o);
        s2 += __shfl_xor_sync(0xffffffffu, s2, o);
    }
    __shared__ double sh[2][8];
    int w = threadIdx.x >> 5, l = threadIdx.x & 31;
    if (l == 0) { sh[0][w] = s; sh[1][w] = s2; }
    __syncthreads();
    if (threadIdx.x == 0) {
        double ts = 0.0, ts2 = 0.0;
        int nw = blockDim.x >> 5;
        for (int i = 0; i < nw; i++) { ts += sh[0][i]; ts2 += sh[1][i]; }
        atomicAdd(&g_red[0], ts);
        atomicAdd(&g_red[1], ts2);
    }
}

// ELU: apply elu. CVT: emit tf32-rounded bits (next GEMM's A operand).
template <bool ELU, bool CVT>
__global__ void normalize_kernel(const float* __restrict__ h,
                                 const float* __restrict__ gamma,
                                 const float* __restrict__ beta,
                                 float* __restrict__ out,
                                 int dmask, long M) {
    double mean = g_red[0] / (double)M;
    double var = g_red[1] / (double)M - mean * mean;
    if (var < 0.0) var = 0.0;
    float inv = 1.0f / ((float)sqrt(var) + 1e-5f);
    float fm = (float)mean;
    long stride = (long)gridDim.x * blockDim.x;
    for (long i = (long)blockIdx.x * blockDim.x + threadIdx.x; i < M; i += stride) {
        int c = (int)(i & dmask);
        float y = (h[i] - fm) * inv * gamma[c] + beta[c];
        if (ELU) y = (y > 0.f) ? y : expm1f(y);
        if (CVT) y = __uint_as_float(f2tf(y));
        out[i] = y;
    }
}

// ---------------- host launcher ----------------
extern "C" void kernel_launch(void* const* d_in, const int* in_sizes, int n_in,
                              void* d_out, int out_size) {
    const float* x    = (const float*)d_in[0];
    const float* Wq1  = (const float*)d_in[1];
    const float* bq1  = (const float*)d_in[2];
    const float* Wk1  = (const float*)d_in[3];
    const float* bk1  = (const float*)d_in[4];
    const float* Wv1  = (const float*)d_in[5];
    const float* bv1  = (const float*)d_in[6];
    const float* Ws1  = (const float*)d_in[7];
    const float* bs1  = (const float*)d_in[8];
    const float* ga1  = (const float*)d_in[9];
    const float* be1  = (const float*)d_in[10];
    const float* Wq2  = (const float*)d_in[11];
    const float* bq2  = (const float*)d_in[12];
    const float* Wk2  = (const float*)d_in[13];
    const float* bk2  = (const float*)d_in[14];
    const float* Wv2  = (const float*)d_in[15];
    const float* bv2  = (const float*)d_in[16];
    const float* Ws2  = (const float*)d_in[17];
    const float* bs2  = (const float*)d_in[18];
    const float* ga2  = (const float*)d_in[19];
    const float* be2  = (const float*)d_in[20];
    const void*  ei   = d_in[21];
    float* out = (float*)d_out;

    void *p_q, *p_k, *p_v, *p_s, *p_h, *p_xc, *p_wc, *p_deg, *p_red, *p_is64;
    cudaGetSymbolAddress(&p_q, g_q);
    cudaGetSymbolAddress(&p_k, g_k);
    cudaGetSymbolAddress(&p_v, g_v);
    cudaGetSymbolAddress(&p_s, g_s);
    cudaGetSymbolAddress(&p_h, g_h);
    cudaGetSymbolAddress(&p_xc, g_xc);
    cudaGetSymbolAddress(&p_wc, g_wc);
    cudaGetSymbolAddress(&p_deg, g_deg);
    cudaGetSymbolAddress(&p_red, g_red);
    cudaGetSymbolAddress(&p_is64, g_is64);

    float* q  = (float*)p_q;
    float* k  = (float*)p_k;
    float* v  = (float*)p_v;
    float* s  = (float*)p_s;
    float* h  = (float*)p_h;
    float* xc = (float*)p_xc;
    float* wc = (float*)p_wc;

    cudaFuncSetAttribute(gemm4_tf32_kernel,
                         cudaFuncAttributeMaxDynamicSharedMemorySize, GEMM_SMEM_BYTES);

    // ---- edge dtype detection + CSR build ----
    cudaMemsetAsync(p_is64, 0xFF, sizeof(int), 0);
    detect_idx_kernel<<<1024, 256>>>((const long long*)ei);
    cudaMemsetAsync(p_deg, 0, N_NODES * sizeof(int), 0);
    cvt_count_kernel<<<2048, 256>>>(ei);
    scan_offsets_kernel<<<1, 1024>>>();
    fill_csr_kernel<<<2048, 256>>>();

    // ---- layer 1: preconvert + fused 4x GEMM ----
    const int W1 = IN_DIM * HID;
    cvt_tf32_kernel<<<2048, 256>>>(x, xc, N_NODES * IN_DIM);
    cvt_tf32_kernel<<<256, 256>>>(Wq1, wc + 0 * W1, W1);
    cvt_tf32_kernel<<<256, 256>>>(Wk1, wc + 1 * W1, W1);
    cvt_tf32_kernel<<<256, 256>>>(Wv1, wc + 2 * W1, W1);
    cvt_tf32_kernel<<<256, 256>>>(Ws1, wc + 3 * W1, W1);
    {
        dim3 grid((N_NODES + 127) / 128, HID / 128, 4);
        gemm4_tf32_kernel<<<grid, 256, GEMM_SMEM_BYTES>>>(
            xc, wc, wc + W1, wc + 2 * W1, wc + 3 * W1,
            bq1, bk1, bv1, bs1, q, k, v, s, N_NODES, HID, IN_DIM);
    }
    score_softmax_kernel<HID, 8><<<N_NODES, 256>>>(q, k, 1.0f / 16.0f);
    node_aggregate_kernel<HID><<<N_NODES, HID>>>(v, s, h);

    cudaMemsetAsync(p_red, 0, 2 * sizeof(double), 0);
    reduce_stats_kernel<<<1024, 256>>>(h, (long)N_NODES * HID);
    // ELU + tf32-convert straight into layer-2's A operand
    normalize_kernel<true, true><<<2048, 256>>>(h, ga1, be1, xc, HID - 1, (long)N_NODES * HID);

    // ---- layer 2 ----
    const int W2 = HID * OUT_DIM;
    cvt_tf32_kernel<<<128, 256>>>(Wq2, wc + 0 * W2, W2);
    cvt_tf32_kernel<<<128, 256>>>(Wk2, wc + 1 * W2, W2);
    cvt_tf32_kernel<<<128, 256>>>(Wv2, wc + 2 * W2, W2);
    cvt_tf32_kernel<<<128, 256>>>(Ws2, wc + 3 * W2, W2);
    {
        dim3 grid((N_NODES + 127) / 128, OUT_DIM / 128, 4);
        gemm4_tf32_kernel<<<grid, 256, GEMM_SMEM_BYTES>>>(
            xc, wc, wc + W2, wc + 2 * W2, wc + 3 * W2,
            bq2, bk2, bv2, bs2, q, k, v, s, N_NODES, OUT_DIM, HID);
    }
    score_softmax_kernel<OUT_DIM, 4><<<N_NODES, 128>>>(q, k, 0.08838834764831845f);
    node_aggregate_kernel<OUT_DIM><<<N_NODES, OUT_DIM>>>(v, s, h);

    cudaMemsetAsync(p_red, 0, 2 * sizeof(double), 0);
    reduce_stats_kernel<<<1024, 256>>>(h, (long)N_NODES * OUT_DIM);
    normalize_kernel<false, false><<<2048, 256>>>(h, ga2, be2, out, OUT_DIM - 1, (long)N_NODES * OUT_DIM);
}

// round 8
// speedup vs baseline: 2.3007x; 1.1675x over previous
#include <cuda_runtime.h>
#include <cuda_fp16.h>
#include <math.h>
#include <stdint.h>

#define N_NODES 50000
#define N_EDGES 800000
#define IN_DIM  512
#define HID     256
#define OUT_DIM 128

// ---------------- scratch (static device globals; no allocation) ----------------
__device__ float    g_q[N_NODES * HID];
__device__ float    g_k[N_NODES * HID];
__device__ float    g_v[N_NODES * HID];
__device__ float    g_s[N_NODES * HID];      // skip (x@Ws+bs)
__device__ float    g_h[N_NODES * HID];      // conv out (pre-LN)
__device__ __half   g_xch[N_NODES * IN_DIM]; // fp16 GEMM A operand
__device__ __half   g_wch[4 * IN_DIM * HID]; // fp16 TRANSPOSED weights [N,K] x4
__device__ float    g_w[N_EDGES];            // CSR-slot-ordered scores -> softmax w
__device__ float    g_dinv[N_NODES];         // 1/denom per node
__device__ int      g_deg[N_NODES];
__device__ int      g_off[N_NODES + 1];
__device__ int      g_cursor[N_NODES];
__device__ int      g_csrsrc[N_EDGES];       // src node per CSR slot
__device__ int      g_src[N_EDGES];
__device__ int      g_dst[N_EDGES];
__device__ double   g_red[2];
__device__ int      g_is64;

// ---------------- edge-index dtype detection ----------------
__global__ void detect_idx_kernel(const long long* __restrict__ ei) {
    int stride = gridDim.x * blockDim.x;
    int bad = 0;
    for (int i = blockIdx.x * blockDim.x + threadIdx.x; i < N_EDGES; i += stride) {
        long long v = ei[i];
        if (v < 0 || v >= N_NODES) bad = 1;
    }
    if (__syncthreads_or(bad) && threadIdx.x == 0) atomicAnd(&g_is64, 0);
}

// ---------------- edge preprocessing ----------------
__global__ void cvt_count_kernel(const void* __restrict__ eiv) {
    const bool is64 = (g_is64 != 0);
    const long long* e64 = (const long long*)eiv;
    const int*       e32 = (const int*)eiv;
    int stride = gridDim.x * blockDim.x;
    for (int e = blockIdx.x * blockDim.x + threadIdx.x; e < N_EDGES; e += stride) {
        long long sv = is64 ? e64[e]           : (long long)e32[e];
        long long dv = is64 ? e64[N_EDGES + e] : (long long)e32[N_EDGES + e];
        int s = (int)sv, d = (int)dv;
        if (s < 0) s = 0; if (s >= N_NODES) s = N_NODES - 1;
        if (d < 0) d = 0; if (d >= N_NODES) d = N_NODES - 1;
        g_src[e] = s;
        g_dst[e] = d;
        atomicAdd(&g_deg[d], 1);
    }
}

__global__ void scan_offsets_kernel() {
    __shared__ int partial[1024];
    int t = threadIdx.x;
    const int C = (N_NODES + 1023) / 1024;
    int lo = t * C;
    int hi = lo + C; if (hi > N_NODES) hi = N_NODES;
    if (lo > N_NODES) lo = N_NODES;
    int s = 0;
    for (int i = lo; i < hi; i++) s += g_deg[i];
    partial[t] = s;
    __syncthreads();
    for (int o = 1; o < 1024; o <<= 1) {
        int add = (t >= o) ? partial[t - o] : 0;
        __syncthreads();
        partial[t] += add;
        __syncthreads();
    }
    int run = partial[t] - s;
    for (int i = lo; i < hi; i++) {
        g_off[i] = run;
        g_cursor[i] = run;
        run += g_deg[i];
    }
    if (t == 1023) g_off[N_NODES] = partial[1023];
}

__global__ void fill_csr_kernel() {
    int stride = gridDim.x * blockDim.x;
    for (int e = blockIdx.x * blockDim.x + threadIdx.x; e < N_EDGES; e += stride) {
        int p = atomicAdd(&g_cursor[g_dst[e]], 1);
        if (p >= 0 && p < N_EDGES) g_csrsrc[p] = g_src[e];
    }
}

// ---------------- fp16 pre-conversion ----------------
__global__ void cvt_f2h_kernel(const float* __restrict__ in, __half* __restrict__ out, int n) {
    int stride = gridDim.x * blockDim.x;
    for (int i = blockIdx.x * blockDim.x + threadIdx.x; i < n; i += stride)
        out[i] = __float2half(in[i]);
}

// W [K,N] row-major -> out [N,K] row-major, fp16
__global__ void cvtT_f2h_kernel(const float* __restrict__ W, __half* __restrict__ out,
                                int K, int N) {
    int stride = gridDim.x * blockDim.x;
    int total = K * N;
    for (int i = blockIdx.x * blockDim.x + threadIdx.x; i < total; i += stride) {
        int k = i / N, n = i - k * N;
        out[n * K + k] = __float2half(W[i]);
    }
}

// ---------------- fp16 tensor-core GEMM (legacy mma.sync m16n8k16) ----------------
// D[M,NTOT] = A[M,K](fp16) @ Bt[NTOT,K](fp16)^T + bias, fp32 accumulate.
// Block tile 128x128 (grid.y covers NTOT/128), 8 warps 2x4, warp tile 64x32.
// BK=32 halfs per stage, 4-stage cp.async. Smem rows stride 40 halfs (80B):
// fragment LDS.32 patterns hit all 32 banks (20-word stride permutation).

__device__ __forceinline__ void mma_f16(float* c, const unsigned* a, const unsigned* b) {
    asm volatile(
        "mma.sync.aligned.m16n8k16.row.col.f32.f16.f16.f32 "
        "{%0,%1,%2,%3}, {%4,%5,%6,%7}, {%8,%9}, {%0,%1,%2,%3};"
        : "+f"(c[0]), "+f"(c[1]), "+f"(c[2]), "+f"(c[3])
        : "r"(a[0]), "r"(a[1]), "r"(a[2]), "r"(a[3]), "r"(b[0]), "r"(b[1]));
}

__device__ __forceinline__ void cpasync16(void* smem, const void* gmem) {
    unsigned saddr = (unsigned)__cvta_generic_to_shared(smem);
    asm volatile("cp.async.ca.shared.global [%0], [%1], 16;" :: "r"(saddr), "l"(gmem));
}

#define HPAD 40      // halfs per smem row (32 data + 8 pad) = 80B
#define HSTAGES 4
#define GEMM_SMEM_BYTES (HSTAGES * 2 * 128 * HPAD * 2)   // 81920

template <int NTOT, int K>
__global__ void __launch_bounds__(256, 2)
gemm4_f16_kernel(const __half* __restrict__ A, const __half* __restrict__ BtAll,
                 const float* __restrict__ c0, const float* __restrict__ c1,
                 const float* __restrict__ c2, const float* __restrict__ c3,
                 float* __restrict__ O0, float* __restrict__ O1,
                 float* __restrict__ O2, float* __restrict__ O3, int M) {
    const float* bias; float* O;
    switch (blockIdx.z) {
        case 0: bias = c0; O = O0; break;
        case 1: bias = c1; O = O1; break;
        case 2: bias = c2; O = O2; break;
        default: bias = c3; O = O3; break;
    }
    const __half* Bt = BtAll + (long)blockIdx.z * NTOT * K;

    extern __shared__ __half hsm[];
    __half (*As)[128][HPAD] = (__half(*)[128][HPAD])hsm;
    __half (*Bs)[128][HPAD] = (__half(*)[128][HPAD])(hsm + HSTAGES * 128 * HPAD);

    int tid = threadIdx.x;
    int lane = tid & 31;
    int wid = tid >> 5;
    int wr = wid >> 2;          // 0..1 (64-row half)
    int wc = wid & 3;           // 0..3 (32-col quarter)
    int grp = lane >> 2;        // 0..7
    int qid = lane & 3;         // 0..3
    int bm = blockIdx.x * 128;
    int bn = blockIdx.y * 128;

    float acc[4][4][4];
#pragma unroll
    for (int i = 0; i < 4; i++)
#pragma unroll
        for (int j = 0; j < 4; j++)
#pragma unroll
            for (int r = 0; r < 4; r++) acc[i][j][r] = 0.f;

    // cp.async indices: 512 16B-chunks per tile (128 rows x 4), 2 per thread per tile
    int r0i = tid >> 2,          c0i = (tid & 3) * 8;     // halfs offset in row
    int r1i = (tid + 256) >> 2,  c1i = (tid & 3) * 8;
    int a_g0 = bm + r0i; if (a_g0 >= M) a_g0 = M - 1;
    int a_g1 = bm + r1i; if (a_g1 >= M) a_g1 = M - 1;
    int b_g0 = bn + r0i, b_g1 = bn + r1i;   // NTOT multiple of 128 -> in range

    const int KT = K / 32;

#define PREFETCH(st, kt_) do { \
        int kb_ = (kt_) * 32; \
        cpasync16(&As[st][r0i][c0i], A + (long)a_g0 * K + kb_ + c0i); \
        cpasync16(&As[st][r1i][c1i], A + (long)a_g1 * K + kb_ + c1i); \
        cpasync16(&Bs[st][r0i][c0i], Bt + (long)b_g0 * K + kb_ + c0i); \
        cpasync16(&Bs[st][r1i][c1i], Bt + (long)b_g1 * K + kb_ + c1i); \
        asm volatile("cp.async.commit_group;"); \
    } while (0)

    for (int st = 0; st < 3 && st < KT; st++) PREFETCH(st, st);

    for (int kt = 0; kt < KT; kt++) {
        int rem = KT - 1 - kt;
        if (rem >= 2)      asm volatile("cp.async.wait_group 2;");
        else if (rem == 1) asm volatile("cp.async.wait_group 1;");
        else               asm volatile("cp.async.wait_group 0;");
        __syncthreads();
        if (kt + 3 < KT) PREFETCH((kt + 3) & 3, kt + 3);
        int buf = kt & 3;

#pragma unroll
        for (int ks = 0; ks < 32; ks += 16) {
            unsigned afr[4][4];
#pragma unroll
            for (int mi = 0; mi < 4; mi++) {
                int row = wr * 64 + mi * 16 + grp;
                afr[mi][0] = *(const unsigned*)&As[buf][row][ks + 2 * qid];
                afr[mi][1] = *(const unsigned*)&As[buf][row + 8][ks + 2 * qid];
                afr[mi][2] = *(const unsigned*)&As[buf][row][ks + 2 * qid + 8];
                afr[mi][3] = *(const unsigned*)&As[buf][row + 8][ks + 2 * qid + 8];
            }
            unsigned bfr[4][2];
#pragma unroll
            for (int ni = 0; ni < 4; ni++) {
                int col = wc * 32 + ni * 8 + grp;
                bfr[ni][0] = *(const unsigned*)&Bs[buf][col][ks + 2 * qid];
                bfr[ni][1] = *(const unsigned*)&Bs[buf][col][ks + 2 * qid + 8];
            }
#pragma unroll
            for (int mi = 0; mi < 4; mi++)
#pragma unroll
                for (int ni = 0; ni < 4; ni++)
                    mma_f16(acc[mi][ni], afr[mi], bfr[ni]);
        }
        __syncthreads();
    }
#undef PREFETCH

#pragma unroll
    for (int mi = 0; mi < 4; mi++) {
        int r0 = bm + wr * 64 + mi * 16 + grp;
#pragma unroll
        for (int ni = 0; ni < 4; ni++) {
            int gc = bn + wc * 32 + ni * 8 + 2 * qid;
            float bz0 = bias[gc], bz1 = bias[gc + 1];
            if (r0 < M) {
                O[(long)r0 * NTOT + gc]     = acc[mi][ni][0] + bz0;
                O[(long)r0 * NTOT + gc + 1] = acc[mi][ni][1] + bz1;
            }
            if (r0 + 8 < M) {
                O[(long)(r0 + 8) * NTOT + gc]     = acc[mi][ni][2] + bz0;
                O[(long)(r0 + 8) * NTOT + gc + 1] = acc[mi][ni][3] + bz1;
            }
        }
    }
}

// ---------------- fused per-node scores + softmax (no atomics) ----------------
template <int D, int WARPS>
__global__ void __launch_bounds__(WARPS * 32)
score_softmax_kernel(const float* __restrict__ q,
                     const float* __restrict__ k,
                     float scale) {
    int n = blockIdx.x;
    __shared__ float qs[D];
    __shared__ float red[WARPS];
    __shared__ float bcast;
    int tid = threadIdx.x, lane = tid & 31, wid = tid >> 5;
    int s0 = g_off[n], s1 = g_off[n + 1];

    for (int i = tid; i < D; i += WARPS * 32) qs[i] = q[(long)n * D + i];
    __syncthreads();

    float lmax = -3.4e38f;
    const float4* qr = (const float4*)qs;
    for (int j = s0 + wid; j < s1; j += WARPS) {
        int src = g_csrsrc[j];
        const float4* kr = (const float4*)(k + (long)src * D);
        float acc = 0.f;
#pragma unroll
        for (int i = 0; i < D / 128; i++) {
            float4 a = qr[lane + 32 * i];
            float4 b = kr[lane + 32 * i];
            acc += a.x * b.x + a.y * b.y + a.z * b.z + a.w * b.w;
        }
#pragma unroll
        for (int o = 16; o > 0; o >>= 1) acc += __shfl_xor_sync(0xffffffffu, acc, o);
        float sc = acc * scale;
        if (lane == 0) g_w[j] = sc;
        lmax = fmaxf(lmax, sc);
    }
    if (lane == 0) red[wid] = lmax;
    __syncthreads();
    if (tid == 0) {
        float m = red[0];
#pragma unroll
        for (int i = 1; i < WARPS; i++) m = fmaxf(m, red[i]);
        bcast = m;
    }
    __syncthreads();
    float m = bcast;

    float lsum = 0.f;
    for (int j = s0 + tid; j < s1; j += WARPS * 32) {
        float w = __expf(g_w[j] - m);
        g_w[j] = w;
        lsum += w;
    }
#pragma unroll
    for (int o = 16; o > 0; o >>= 1) lsum += __shfl_xor_sync(0xffffffffu, lsum, o);
    if (lane == 0) red[wid] = lsum;
    __syncthreads();
    if (tid == 0) {
        float sum = 0.f;
#pragma unroll
        for (int i = 0; i < WARPS; i++) sum += red[i];
        g_dinv[n] = (sum > 0.f) ? 1.f / sum : 0.f;
    }
}

// out[n][c] = skip[n][c] + dinv[n] * sum_j w[j] * v[src[j]][c]
template <int D>
__global__ void node_aggregate_kernel(const float* __restrict__ v,
                                      const float* __restrict__ skip,
                                      float* __restrict__ out) {
    int n = blockIdx.x;
    int c = threadIdx.x;
    int s0 = g_off[n], s1 = g_off[n + 1];
    float inv = g_dinv[n];
    float acc0 = 0.f, acc1 = 0.f;
    int j = s0;
    for (; j + 1 < s1; j += 2) {
        int sa = g_csrsrc[j], sb = g_csrsrc[j + 1];
        float wa = g_w[j], wb = g_w[j + 1];
        acc0 += wa * v[(long)sa * D + c];
        acc1 += wb * v[(long)sb * D + c];
    }
    if (j < s1) acc0 += g_w[j] * v[(long)g_csrsrc[j] * D + c];
    out[(long)n * D + c] = skip[(long)n * D + c] + (acc0 + acc1) * inv;
}

// ---------------- graph layer norm ----------------
__global__ void reduce_stats_kernel(const float* __restrict__ h, long M) {
    double s = 0.0, s2 = 0.0;
    long stride = (long)gridDim.x * blockDim.x;
    for (long i = (long)blockIdx.x * blockDim.x + threadIdx.x; i < M; i += stride) {
        float xv = h[i];
        s += (double)xv;
        s2 += (double)xv * (double)xv;
    }
#pragma unroll
    for (int o = 16; o > 0; o >>= 1) {
        s += __shfl_xor_sync(0xffffffffu, s, o);
        s2 += __shfl_xor_sync(0xffffffffu, s2, o);
    }
    __shared__ double sh[2][8];
    int w = threadIdx.x >> 5, l = threadIdx.x & 31;
    if (l == 0) { sh[0][w] = s; sh[1][w] = s2; }
    __syncthreads();
    if (threadIdx.x == 0) {
        double ts = 0.0, ts2 = 0.0;
        int nw = blockDim.x >> 5;
        for (int i = 0; i < nw; i++) { ts += sh[0][i]; ts2 += sh[1][i]; }
        atomicAdd(&g_red[0], ts);
        atomicAdd(&g_red[1], ts2);
    }
}

// ELU + write fp16 (layer-2 A operand)
__global__ void normalize_elu_h_kernel(const float* __restrict__ h,
                                       const float* __restrict__ gamma,
                                       const float* __restrict__ beta,
                                       __half* __restrict__ out,
                                       int dmask, long M) {
    double mean = g_red[0] / (double)M;
    double var = g_red[1] / (double)M - mean * mean;
    if (var < 0.0) var = 0.0;
    float inv = 1.0f / ((float)sqrt(var) + 1e-5f);
    float fm = (float)mean;
    long stride = (long)gridDim.x * blockDim.x;
    for (long i = (long)blockIdx.x * blockDim.x + threadIdx.x; i < M; i += stride) {
        int c = (int)(i & dmask);
        float y = (h[i] - fm) * inv * gamma[c] + beta[c];
        y = (y > 0.f) ? y : expm1f(y);
        out[i] = __float2half(y);
    }
}

__global__ void normalize_f_kernel(const float* __restrict__ h,
                                   const float* __restrict__ gamma,
                                   const float* __restrict__ beta,
                                   float* __restrict__ out,
                                   int dmask, long M) {
    double mean = g_red[0] / (double)M;
    double var = g_red[1] / (double)M - mean * mean;
    if (var < 0.0) var = 0.0;
    float inv = 1.0f / ((float)sqrt(var) + 1e-5f);
    float fm = (float)mean;
    long stride = (long)gridDim.x * blockDim.x;
    for (long i = (long)blockIdx.x * blockDim.x + threadIdx.x; i < M; i += stride) {
        int c = (int)(i & dmask);
        out[i] = (h[i] - fm) * inv * gamma[c] + beta[c];
    }
}

// ---------------- host launcher ----------------
extern "C" void kernel_launch(void* const* d_in, const int* in_sizes, int n_in,
                              void* d_out, int out_size) {
    const float* x    = (const float*)d_in[0];
    const float* Wq1  = (const float*)d_in[1];
    const float* bq1  = (const float*)d_in[2];
    const float* Wk1  = (const float*)d_in[3];
    const float* bk1  = (const float*)d_in[4];
    const float* Wv1  = (const float*)d_in[5];
    const float* bv1  = (const float*)d_in[6];
    const float* Ws1  = (const float*)d_in[7];
    const float* bs1  = (const float*)d_in[8];
    const float* ga1  = (const float*)d_in[9];
    const float* be1  = (const float*)d_in[10];
    const float* Wq2  = (const float*)d_in[11];
    const float* bq2  = (const float*)d_in[12];
    const float* Wk2  = (const float*)d_in[13];
    const float* bk2  = (const float*)d_in[14];
    const float* Wv2  = (const float*)d_in[15];
    const float* bv2  = (const float*)d_in[16];
    const float* Ws2  = (const float*)d_in[17];
    const float* bs2  = (const float*)d_in[18];
    const float* ga2  = (const float*)d_in[19];
    const float* be2  = (const float*)d_in[20];
    const void*  ei   = d_in[21];
    float* out = (float*)d_out;

    void *p_q, *p_k, *p_v, *p_s, *p_h, *p_xch, *p_wch, *p_deg, *p_red, *p_is64;
    cudaGetSymbolAddress(&p_q, g_q);
    cudaGetSymbolAddress(&p_k, g_k);
    cudaGetSymbolAddress(&p_v, g_v);
    cudaGetSymbolAddress(&p_s, g_s);
    cudaGetSymbolAddress(&p_h, g_h);
    cudaGetSymbolAddress(&p_xch, g_xch);
    cudaGetSymbolAddress(&p_wch, g_wch);
    cudaGetSymbolAddress(&p_deg, g_deg);
    cudaGetSymbolAddress(&p_red, g_red);
    cudaGetSymbolAddress(&p_is64, g_is64);

    float*  q  = (float*)p_q;
    float*  k  = (float*)p_k;
    float*  v  = (float*)p_v;
    float*  s  = (float*)p_s;
    float*  h  = (float*)p_h;
    __half* xh = (__half*)p_xch;
    __half* wh = (__half*)p_wch;

    cudaFuncSetAttribute(gemm4_f16_kernel<HID, IN_DIM>,
                         cudaFuncAttributeMaxDynamicSharedMemorySize, GEMM_SMEM_BYTES);
    cudaFuncSetAttribute(gemm4_f16_kernel<OUT_DIM, HID>,
                         cudaFuncAttributeMaxDynamicSharedMemorySize, GEMM_SMEM_BYTES);

    // ---- edge dtype detection + CSR build ----
    cudaMemsetAsync(p_is64, 0xFF, sizeof(int), 0);
    detect_idx_kernel<<<1024, 256>>>((const long long*)ei);
    cudaMemsetAsync(p_deg, 0, N_NODES * sizeof(int), 0);
    cvt_count_kernel<<<2048, 256>>>(ei);
    scan_offsets_kernel<<<1, 1024>>>();
    fill_csr_kernel<<<2048, 256>>>();

    // ---- layer 1: preconvert (fp16) + fused 4x GEMM ----
    const int W1 = IN_DIM * HID;
    cvt_f2h_kernel<<<2048, 256>>>(x, xh, N_NODES * IN_DIM);
    cvtT_f2h_kernel<<<256, 256>>>(Wq1, wh + 0 * W1, IN_DIM, HID);
    cvtT_f2h_kernel<<<256, 256>>>(Wk1, wh + 1 * W1, IN_DIM, HID);
    cvtT_f2h_kernel<<<256, 256>>>(Wv1, wh + 2 * W1, IN_DIM, HID);
    cvtT_f2h_kernel<<<256, 256>>>(Ws1, wh + 3 * W1, IN_DIM, HID);
    {
        dim3 grid((N_NODES + 127) / 128, HID / 128, 4);
        gemm4_f16_kernel<HID, IN_DIM><<<grid, 256, GEMM_SMEM_BYTES>>>(
            xh, wh, bq1, bk1, bv1, bs1, q, k, v, s, N_NODES);
    }
    score_softmax_kernel<HID, 8><<<N_NODES, 256>>>(q, k, 1.0f / 16.0f);
    node_aggregate_kernel<HID><<<N_NODES, HID>>>(v, s, h);

    cudaMemsetAsync(p_red, 0, 2 * sizeof(double), 0);
    reduce_stats_kernel<<<1024, 256>>>(h, (long)N_NODES * HID);
    normalize_elu_h_kernel<<<2048, 256>>>(h, ga1, be1, xh, HID - 1, (long)N_NODES * HID);

    // ---- layer 2 ----
    const int W2 = HID * OUT_DIM;
    cvtT_f2h_kernel<<<128, 256>>>(Wq2, wh + 0 * W2, HID, OUT_DIM);
    cvtT_f2h_kernel<<<128, 256>>>(Wk2, wh + 1 * W2, HID, OUT_DIM);
    cvtT_f2h_kernel<<<128, 256>>>(Wv2, wh + 2 * W2, HID, OUT_DIM);
    cvtT_f2h_kernel<<<128, 256>>>(Ws2, wh + 3 * W2, HID, OUT_DIM);
    {
        dim3 grid((N_NODES + 127) / 128, OUT_DIM / 128, 4);
        gemm4_f16_kernel<OUT_DIM, HID><<<grid, 256, GEMM_SMEM_BYTES>>>(
            xh, wh, bq2, bk2, bv2, bs2, q, k, v, s, N_NODES);
    }
    score_softmax_kernel<OUT_DIM, 4><<<N_NODES, 128>>>(q, k, 0.08838834764831845f);
    node_aggregate_kernel<OUT_DIM><<<N_NODES, OUT_DIM>>>(v, s, h);

    cudaMemsetAsync(p_red, 0, 2 * sizeof(double), 0);
    reduce_stats_kernel<<<1024, 256>>>(h, (long)N_NODES * OUT_DIM);
    normalize_f_kernel<<<2048, 256>>>(h, ga2, be2, out, OUT_DIM - 1, (long)N_NODES * OUT_DIM);
}

// round 9
// speedup vs baseline: 2.5749x; 1.1192x over previous
#include <cuda_runtime.h>
#include <cuda_fp16.h>
#include <math.h>
#include <stdint.h>

#define N_NODES 50000
#define N_EDGES 800000
#define IN_DIM  512
#define HID     256
#define OUT_DIM 128

// ---------------- scratch (static device globals; no allocation) ----------------
__device__ __half   g_qh[N_NODES * HID];     // q fp16 (score input)
__device__ __half   g_kh[N_NODES * HID];     // k fp16 (score gather)
__device__ __half   g_vh[N_NODES * HID];     // v fp16 (aggregate gather)
__device__ float    g_s[N_NODES * HID];      // skip (x@Ws+bs), fp32
__device__ float    g_h[N_NODES * HID];      // conv out (pre-LN)
__device__ __half   g_xch[N_NODES * IN_DIM]; // fp16 GEMM A operand
__device__ __half   g_wch[4 * IN_DIM * HID]; // fp16 TRANSPOSED weights [N,K] x4
__device__ float    g_w[N_EDGES];            // CSR-slot scores -> softmax w
__device__ float    g_dinv[N_NODES];
__device__ int      g_deg[N_NODES];
__device__ int      g_off[N_NODES + 1];
__device__ int      g_cursor[N_NODES];
__device__ int      g_csrsrc[N_EDGES];
__device__ int      g_src[N_EDGES];
__device__ int      g_dst[N_EDGES];
__device__ double   g_red[2];
__device__ int      g_is64;

// ---------------- edge-index dtype detection ----------------
__global__ void detect_idx_kernel(const long long* __restrict__ ei) {
    int stride = gridDim.x * blockDim.x;
    int bad = 0;
    for (int i = blockIdx.x * blockDim.x + threadIdx.x; i < N_EDGES; i += stride) {
        long long v = ei[i];
        if (v < 0 || v >= N_NODES) bad = 1;
    }
    if (__syncthreads_or(bad) && threadIdx.x == 0) atomicAnd(&g_is64, 0);
}

__global__ void cvt_count_kernel(const void* __restrict__ eiv) {
    const bool is64 = (g_is64 != 0);
    const long long* e64 = (const long long*)eiv;
    const int*       e32 = (const int*)eiv;
    int stride = gridDim.x * blockDim.x;
    for (int e = blockIdx.x * blockDim.x + threadIdx.x; e < N_EDGES; e += stride) {
        long long sv = is64 ? e64[e]           : (long long)e32[e];
        long long dv = is64 ? e64[N_EDGES + e] : (long long)e32[N_EDGES + e];
        int s = (int)sv, d = (int)dv;
        if (s < 0) s = 0; if (s >= N_NODES) s = N_NODES - 1;
        if (d < 0) d = 0; if (d >= N_NODES) d = N_NODES - 1;
        g_src[e] = s;
        g_dst[e] = d;
        atomicAdd(&g_deg[d], 1);
    }
}

__global__ void scan_offsets_kernel() {
    __shared__ int partial[1024];
    int t = threadIdx.x;
    const int C = (N_NODES + 1023) / 1024;
    int lo = t * C;
    int hi = lo + C; if (hi > N_NODES) hi = N_NODES;
    if (lo > N_NODES) lo = N_NODES;
    int s = 0;
    for (int i = lo; i < hi; i++) s += g_deg[i];
    partial[t] = s;
    __syncthreads();
    for (int o = 1; o < 1024; o <<= 1) {
        int add = (t >= o) ? partial[t - o] : 0;
        __syncthreads();
        partial[t] += add;
        __syncthreads();
    }
    int run = partial[t] - s;
    for (int i = lo; i < hi; i++) {
        g_off[i] = run;
        g_cursor[i] = run;
        run += g_deg[i];
    }
    if (t == 1023) g_off[N_NODES] = partial[1023];
}

__global__ void fill_csr_kernel() {
    int stride = gridDim.x * blockDim.x;
    for (int e = blockIdx.x * blockDim.x + threadIdx.x; e < N_EDGES; e += stride) {
        int p = atomicAdd(&g_cursor[g_dst[e]], 1);
        if (p >= 0 && p < N_EDGES) g_csrsrc[p] = g_src[e];
    }
}

// ---------------- fp16 pre-conversion ----------------
__global__ void cvt_f2h_kernel(const float* __restrict__ in, __half* __restrict__ out, int n) {
    int stride = gridDim.x * blockDim.x;
    for (int i = blockIdx.x * blockDim.x + threadIdx.x; i < n; i += stride)
        out[i] = __float2half(in[i]);
}

__global__ void cvtT_f2h_kernel(const float* __restrict__ W, __half* __restrict__ out,
                                int K, int N) {
    int stride = gridDim.x * blockDim.x;
    int total = K * N;
    for (int i = blockIdx.x * blockDim.x + threadIdx.x; i < total; i += stride) {
        int k = i / N, n = i - k * N;
        out[n * K + k] = __float2half(W[i]);
    }
}

// ---------------- fp16 tensor-core GEMM (mma.sync m16n8k16 + ldmatrix) ----------------
__device__ __forceinline__ void mma_f16(float* c, const unsigned* a, const unsigned* b) {
    asm volatile(
        "mma.sync.aligned.m16n8k16.row.col.f32.f16.f16.f32 "
        "{%0,%1,%2,%3}, {%4,%5,%6,%7}, {%8,%9}, {%0,%1,%2,%3};"
        : "+f"(c[0]), "+f"(c[1]), "+f"(c[2]), "+f"(c[3])
        : "r"(a[0]), "r"(a[1]), "r"(a[2]), "r"(a[3]), "r"(b[0]), "r"(b[1]));
}

__device__ __forceinline__ void ldsm_x4(unsigned* r, uint32_t saddr) {
    asm volatile("ldmatrix.sync.aligned.m8n8.x4.shared.b16 {%0,%1,%2,%3}, [%4];"
        : "=r"(r[0]), "=r"(r[1]), "=r"(r[2]), "=r"(r[3]) : "r"(saddr));
}

__device__ __forceinline__ void ldsm_x2(unsigned* r, uint32_t saddr) {
    asm volatile("ldmatrix.sync.aligned.m8n8.x2.shared.b16 {%0,%1}, [%2];"
        : "=r"(r[0]), "=r"(r[1]) : "r"(saddr));
}

__device__ __forceinline__ void cpasync16(void* smem, const void* gmem) {
    unsigned saddr = (unsigned)__cvta_generic_to_shared(smem);
    asm volatile("cp.async.ca.shared.global [%0], [%1], 16;" :: "r"(saddr), "l"(gmem));
}

#define HPAD 40      // halfs per smem row (32 data + 8 pad) = 80B; conflict-free
#define HSTAGES 4
#define GEMM_SMEM_BYTES (HSTAGES * 2 * 128 * HPAD * 2)   // 81920

// D = A @ Bt^T + bias. Outputs z=0..2 are __half (q,k,v), z=3 is float (s).
template <int NTOT, int K>
__global__ void __launch_bounds__(256, 2)
gemm4_f16_kernel(const __half* __restrict__ A, const __half* __restrict__ BtAll,
                 const float* __restrict__ c0, const float* __restrict__ c1,
                 const float* __restrict__ c2, const float* __restrict__ c3,
                 void* __restrict__ O0, void* __restrict__ O1,
                 void* __restrict__ O2, void* __restrict__ O3, int M) {
    const float* bias; void* Ov;
    switch (blockIdx.z) {
        case 0: bias = c0; Ov = O0; break;
        case 1: bias = c1; Ov = O1; break;
        case 2: bias = c2; Ov = O2; break;
        default: bias = c3; Ov = O3; break;
    }
    const bool halfOut = (blockIdx.z < 3);
    const __half* Bt = BtAll + (long)blockIdx.z * NTOT * K;

    extern __shared__ __half hsm[];
    __half (*As)[128][HPAD] = (__half(*)[128][HPAD])hsm;
    __half (*Bs)[128][HPAD] = (__half(*)[128][HPAD])(hsm + HSTAGES * 128 * HPAD);

    int tid = threadIdx.x;
    int lane = tid & 31;
    int wid = tid >> 5;
    int wr = wid >> 2;
    int wc = wid & 3;
    int grp = lane >> 2;
    int qid = lane & 3;
    int bm = blockIdx.x * 128;
    int bn = blockIdx.y * 128;

    float acc[4][4][4];
#pragma unroll
    for (int i = 0; i < 4; i++)
#pragma unroll
        for (int j = 0; j < 4; j++)
#pragma unroll
            for (int r = 0; r < 4; r++) acc[i][j][r] = 0.f;

    int r0i = tid >> 2,          c0i = (tid & 3) * 8;
    int r1i = (tid + 256) >> 2,  c1i = (tid & 3) * 8;
    int a_g0 = bm + r0i; if (a_g0 >= M) a_g0 = M - 1;
    int a_g1 = bm + r1i; if (a_g1 >= M) a_g1 = M - 1;
    int b_g0 = bn + r0i, b_g1 = bn + r1i;

    // ldmatrix lane addressing (canonical): A x4 -> row = base+(lane&15), k += 8*(lane>>4)
    //                                       B x2 -> col = base+(lane&7),  k += 8*((lane>>3)&1)
    int a_lrow = wr * 64 + (lane & 15);
    int a_lk   = 8 * (lane >> 4);
    int b_lcol = wc * 32 + (lane & 7);
    int b_lk   = 8 * ((lane >> 3) & 1);

    const int KT = K / 32;

#define PREFETCH(st, kt_) do { \
        int kb_ = (kt_) * 32; \
        cpasync16(&As[st][r0i][c0i], A + (long)a_g0 * K + kb_ + c0i); \
        cpasync16(&As[st][r1i][c1i], A + (long)a_g1 * K + kb_ + c1i); \
        cpasync16(&Bs[st][r0i][c0i], Bt + (long)b_g0 * K + kb_ + c0i); \
        cpasync16(&Bs[st][r1i][c1i], Bt + (long)b_g1 * K + kb_ + c1i); \
        asm volatile("cp.async.commit_group;"); \
    } while (0)

    for (int st = 0; st < 3 && st < KT; st++) PREFETCH(st, st);

    for (int kt = 0; kt < KT; kt++) {
        int rem = KT - 1 - kt;
        if (rem >= 2)      asm volatile("cp.async.wait_group 2;");
        else if (rem == 1) asm volatile("cp.async.wait_group 1;");
        else               asm volatile("cp.async.wait_group 0;");
        __syncthreads();
        if (kt + 3 < KT) PREFETCH((kt + 3) & 3, kt + 3);
        int buf = kt & 3;

        uint32_t asb = (uint32_t)__cvta_generic_to_shared(&As[buf][0][0]);
        uint32_t bsb = (uint32_t)__cvta_generic_to_shared(&Bs[buf][0][0]);

#pragma unroll
        for (int ks = 0; ks < 32; ks += 16) {
            unsigned afr[4][4];
#pragma unroll
            for (int mi = 0; mi < 4; mi++)
                ldsm_x4(afr[mi], asb + ((a_lrow + mi * 16) * HPAD + ks + a_lk) * 2);
            unsigned bfr[4][2];
#pragma unroll
            for (int ni = 0; ni < 4; ni++)
                ldsm_x2(bfr[ni], bsb + ((b_lcol + ni * 8) * HPAD + ks + b_lk) * 2);
#pragma unroll
            for (int mi = 0; mi < 4; mi++)
#pragma unroll
                for (int ni = 0; ni < 4; ni++)
                    mma_f16(acc[mi][ni], afr[mi], bfr[ni]);
        }
        __syncthreads();
    }
#undef PREFETCH

#pragma unroll
    for (int mi = 0; mi < 4; mi++) {
        int r0 = bm + wr * 64 + mi * 16 + grp;
#pragma unroll
        for (int ni = 0; ni < 4; ni++) {
            int gc = bn + wc * 32 + ni * 8 + 2 * qid;
            float bz0 = bias[gc], bz1 = bias[gc + 1];
            if (halfOut) {
                __half* Oh = (__half*)Ov;
                if (r0 < M)
                    *(__half2*)&Oh[(long)r0 * NTOT + gc] =
                        __floats2half2_rn(acc[mi][ni][0] + bz0, acc[mi][ni][1] + bz1);
                if (r0 + 8 < M)
                    *(__half2*)&Oh[(long)(r0 + 8) * NTOT + gc] =
                        __floats2half2_rn(acc[mi][ni][2] + bz0, acc[mi][ni][3] + bz1);
            } else {
                float* Of = (float*)Ov;
                if (r0 < M) {
                    Of[(long)r0 * NTOT + gc]     = acc[mi][ni][0] + bz0;
                    Of[(long)r0 * NTOT + gc + 1] = acc[mi][ni][1] + bz1;
                }
                if (r0 + 8 < M) {
                    Of[(long)(r0 + 8) * NTOT + gc]     = acc[mi][ni][2] + bz0;
                    Of[(long)(r0 + 8) * NTOT + gc + 1] = acc[mi][ni][3] + bz1;
                }
            }
        }
    }
}

// ---------------- fused per-node scores + softmax (fp16 gathers) ----------------
template <int D, int WARPS>
__global__ void __launch_bounds__(WARPS * 32)
score_softmax_kernel(const __half* __restrict__ q,
                     const __half* __restrict__ k,
                     float scale) {
    int n = blockIdx.x;
    __shared__ __half2 qs[D / 2];
    __shared__ float red[WARPS];
    __shared__ float bcast;
    int tid = threadIdx.x, lane = tid & 31, wid = tid >> 5;
    int s0 = g_off[n], s1 = g_off[n + 1];

    const __half2* q2 = (const __half2*)(q + (long)n * D);
    for (int i = tid; i < D / 2; i += WARPS * 32) qs[i] = q2[i];
    __syncthreads();

    float lmax = -3.4e38f;
    for (int j = s0 + wid; j < s1; j += WARPS) {
        int src = g_csrsrc[j];
        const __half2* kr = (const __half2*)(k + (long)src * D);
        float acc = 0.f;
#pragma unroll
        for (int i = 0; i < D / 64; i++) {
            float2 a = __half22float2(qs[lane + 32 * i]);
            float2 b = __half22float2(kr[lane + 32 * i]);
            acc += a.x * b.x + a.y * b.y;
        }
#pragma unroll
        for (int o = 16; o > 0; o >>= 1) acc += __shfl_xor_sync(0xffffffffu, acc, o);
        float sc = acc * scale;
        if (lane == 0) g_w[j] = sc;
        lmax = fmaxf(lmax, sc);
    }
    if (lane == 0) red[wid] = lmax;
    __syncthreads();
    if (tid == 0) {
        float m = red[0];
#pragma unroll
        for (int i = 1; i < WARPS; i++) m = fmaxf(m, red[i]);
        bcast = m;
    }
    __syncthreads();
    float m = bcast;

    float lsum = 0.f;
    for (int j = s0 + tid; j < s1; j += WARPS * 32) {
        float w = __expf(g_w[j] - m);
        g_w[j] = w;
        lsum += w;
    }
#pragma unroll
    for (int o = 16; o > 0; o >>= 1) lsum += __shfl_xor_sync(0xffffffffu, lsum, o);
    if (lane == 0) red[wid] = lsum;
    __syncthreads();
    if (tid == 0) {
        float sum = 0.f;
#pragma unroll
        for (int i = 0; i < WARPS; i++) sum += red[i];
        g_dinv[n] = (sum > 0.f) ? 1.f / sum : 0.f;
    }
}

// out[n][c] = skip[n][c] + dinv[n] * sum_j w[j] * v[src[j]][c]; v is fp16, half2 lanes
template <int D>
__global__ void __launch_bounds__(D / 2)
node_aggregate_kernel(const __half* __restrict__ v,
                      const float* __restrict__ skip,
                      float* __restrict__ out) {
    int n = blockIdx.x;
    int c2 = threadIdx.x;                  // half2 index, 0..D/2-1
    int s0 = g_off[n], s1 = g_off[n + 1];
    float inv = g_dinv[n];
    float ax = 0.f, ay = 0.f;
    const __half2* v2 = (const __half2*)v;
    for (int j = s0; j < s1; j++) {
        int src = g_csrsrc[j];
        float we = g_w[j];
        float2 vv = __half22float2(v2[(long)src * (D / 2) + c2]);
        ax += we * vv.x;
        ay += we * vv.y;
    }
    long base = (long)n * D + 2 * c2;
    out[base]     = skip[base]     + ax * inv;
    out[base + 1] = skip[base + 1] + ay * inv;
}

// ---------------- graph layer norm ----------------
__global__ void reduce_stats_kernel(const float* __restrict__ h, long M) {
    double s = 0.0, s2 = 0.0;
    long stride = (long)gridDim.x * blockDim.x;
    for (long i = (long)blockIdx.x * blockDim.x + threadIdx.x; i < M; i += stride) {
        float xv = h[i];
        s += (double)xv;
        s2 += (double)xv * (double)xv;
    }
#pragma unroll
    for (int o = 16; o > 0; o >>= 1) {
        s += __shfl_xor_sync(0xffffffffu, s, o);
        s2 += __shfl_xor_sync(0xffffffffu, s2, o);
    }
    __shared__ double sh[2][8];
    int w = threadIdx.x >> 5, l = threadIdx.x & 31;
    if (l == 0) { sh[0][w] = s; sh[1][w] = s2; }
    __syncthreads();
    if (threadIdx.x == 0) {
        double ts = 0.0, ts2 = 0.0;
        int nw = blockDim.x >> 5;
        for (int i = 0; i < nw; i++) { ts += sh[0][i]; ts2 += sh[1][i]; }
        atomicAdd(&g_red[0], ts);
        atomicAdd(&g_red[1], ts2);
    }
}

__global__ void normalize_elu_h_kernel(const float* __restrict__ h,
                                       const float* __restrict__ gamma,
                                       const float* __restrict__ beta,
                                       __half* __restrict__ out,
                                       int dmask, long M) {
    double mean = g_red[0] / (double)M;
    double var = g_red[1] / (double)M - mean * mean;
    if (var < 0.0) var = 0.0;
    float inv = 1.0f / ((float)sqrt(var) + 1e-5f);
    float fm = (float)mean;
    long stride = (long)gridDim.x * blockDim.x;
    for (long i = (long)blockIdx.x * blockDim.x + threadIdx.x; i < M; i += stride) {
        int c = (int)(i & dmask);
        float y = (h[i] - fm) * inv * gamma[c] + beta[c];
        y = (y > 0.f) ? y : expm1f(y);
        out[i] = __float2half(y);
    }
}

__global__ void normalize_f_kernel(const float* __restrict__ h,
                                   const float* __restrict__ gamma,
                                   const float* __restrict__ beta,
                                   float* __restrict__ out,
                                   int dmask, long M) {
    double mean = g_red[0] / (double)M;
    double var = g_red[1] / (double)M - mean * mean;
    if (var < 0.0) var = 0.0;
    float inv = 1.0f / ((float)sqrt(var) + 1e-5f);
    float fm = (float)mean;
    long stride = (long)gridDim.x * blockDim.x;
    for (long i = (long)blockIdx.x * blockDim.x + threadIdx.x; i < M; i += stride) {
        int c = (int)(i & dmask);
        out[i] = (h[i] - fm) * inv * gamma[c] + beta[c];
    }
}

// ---------------- host launcher ----------------
extern "C" void kernel_launch(void* const* d_in, const int* in_sizes, int n_in,
                              void* d_out, int out_size) {
    const float* x    = (const float*)d_in[0];
    const float* Wq1  = (const float*)d_in[1];
    const float* bq1  = (const float*)d_in[2];
    const float* Wk1  = (const float*)d_in[3];
    const float* bk1  = (const float*)d_in[4];
    const float* Wv1  = (const float*)d_in[5];
    const float* bv1  = (const float*)d_in[6];
    const float* Ws1  = (const float*)d_in[7];
    const float* bs1  = (const float*)d_in[8];
    const float* ga1  = (const float*)d_in[9];
    const float* be1  = (const float*)d_in[10];
    const float* Wq2  = (const float*)d_in[11];
    const float* bq2  = (const float*)d_in[12];
    const float* Wk2  = (const float*)d_in[13];
    const float* bk2  = (const float*)d_in[14];
    const float* Wv2  = (const float*)d_in[15];
    const float* bv2  = (const float*)d_in[16];
    const float* Ws2  = (const float*)d_in[17];
    const float* bs2  = (const float*)d_in[18];
    const float* ga2  = (const float*)d_in[19];
    const float* be2  = (const float*)d_in[20];
    const void*  ei   = d_in[21];
    float* out = (float*)d_out;

    void *p_qh, *p_kh, *p_vh, *p_s, *p_h, *p_xch, *p_wch, *p_deg, *p_red, *p_is64;
    cudaGetSymbolAddress(&p_qh, g_qh);
    cudaGetSymbolAddress(&p_kh, g_kh);
    cudaGetSymbolAddress(&p_vh, g_vh);
    cudaGetSymbolAddress(&p_s, g_s);
    cudaGetSymbolAddress(&p_h, g_h);
    cudaGetSymbolAddress(&p_xch, g_xch);
    cudaGetSymbolAddress(&p_wch, g_wch);
    cudaGetSymbolAddress(&p_deg, g_deg);
    cudaGetSymbolAddress(&p_red, g_red);
    cudaGetSymbolAddress(&p_is64, g_is64);

    __half* qh = (__half*)p_qh;
    __half* kh = (__half*)p_kh;
    __half* vh = (__half*)p_vh;
    float*  s  = (float*)p_s;
    float*  h  = (float*)p_h;
    __half* xh = (__half*)p_xch;
    __half* wh = (__half*)p_wch;

    cudaFuncSetAttribute(gemm4_f16_kernel<HID, IN_DIM>,
                         cudaFuncAttributeMaxDynamicSharedMemorySize, GEMM_SMEM_BYTES);
    cudaFuncSetAttribute(gemm4_f16_kernel<OUT_DIM, HID>,
                         cudaFuncAttributeMaxDynamicSharedMemorySize, GEMM_SMEM_BYTES);

    // ---- edge dtype detection + CSR build ----
    cudaMemsetAsync(p_is64, 0xFF, sizeof(int), 0);
    detect_idx_kernel<<<1024, 256>>>((const long long*)ei);
    cudaMemsetAsync(p_deg, 0, N_NODES * sizeof(int), 0);
    cvt_count_kernel<<<2048, 256>>>(ei);
    scan_offsets_kernel<<<1, 1024>>>();
    fill_csr_kernel<<<2048, 256>>>();

    // ---- layer 1 ----
    const int W1 = IN_DIM * HID;
    cvt_f2h_kernel<<<2048, 256>>>(x, xh, N_NODES * IN_DIM);
    cvtT_f2h_kernel<<<256, 256>>>(Wq1, wh + 0 * W1, IN_DIM, HID);
    cvtT_f2h_kernel<<<256, 256>>>(Wk1, wh + 1 * W1, IN_DIM, HID);
    cvtT_f2h_kernel<<<256, 256>>>(Wv1, wh + 2 * W1, IN_DIM, HID);
    cvtT_f2h_kernel<<<256, 256>>>(Ws1, wh + 3 * W1, IN_DIM, HID);
    {
        dim3 grid((N_NODES + 127) / 128, HID / 128, 4);
        gemm4_f16_kernel<HID, IN_DIM><<<grid, 256, GEMM_SMEM_BYTES>>>(
            xh, wh, bq1, bk1, bv1, bs1, qh, kh, vh, s, N_NODES);
    }
    score_softmax_kernel<HID, 8><<<N_NODES, 256>>>(qh, kh, 1.0f / 16.0f);
    node_aggregate_kernel<HID><<<N_NODES, HID / 2>>>(vh, s, h);

    cudaMemsetAsync(p_red, 0, 2 * sizeof(double), 0);
    reduce_stats_kernel<<<1024, 256>>>(h, (long)N_NODES * HID);
    normalize_elu_h_kernel<<<2048, 256>>>(h, ga1, be1, xh, HID - 1, (long)N_NODES * HID);

    // ---- layer 2 ----
    const int W2 = HID * OUT_DIM;
    cvtT_f2h_kernel<<<128, 256>>>(Wq2, wh + 0 * W2, HID, OUT_DIM);
    cvtT_f2h_kernel<<<128, 256>>>(Wk2, wh + 1 * W2, HID, OUT_DIM);
    cvtT_f2h_kernel<<<128, 256>>>(Wv2, wh + 2 * W2, HID, OUT_DIM);
    cvtT_f2h_kernel<<<128, 256>>>(Ws2, wh + 3 * W2, HID, OUT_DIM);
    {
        dim3 grid((N_NODES + 127) / 128, OUT_DIM / 128, 4);
        gemm4_f16_kernel<OUT_DIM, HID><<<grid, 256, GEMM_SMEM_BYTES>>>(
            xh, wh, bq2, bk2, bv2, bs2, qh, kh, vh, s, N_NODES);
    }
    score_softmax_kernel<OUT_DIM, 4><<<N_NODES, 128>>>(qh, kh, 0.08838834764831845f);
    node_aggregate_kernel<OUT_DIM><<<N_NODES, OUT_DIM / 2>>>(vh, s, h);

    cudaMemsetAsync(p_red, 0, 2 * sizeof(double), 0);
    reduce_stats_kernel<<<1024, 256>>>(h, (long)N_NODES * OUT_DIM);
    normalize_f_kernel<<<2048, 256>>>(h, ga2, be2, out, OUT_DIM - 1, (long)N_NODES * OUT_DIM);
}

// round 10
// speedup vs baseline: 2.9901x; 1.1613x over previous
#include <cuda_runtime.h>
#include <cuda_fp16.h>
#include <math.h>
#include <stdint.h>

#define N_NODES 50000
#define N_EDGES 800000
#define IN_DIM  512
#define HID     256
#define OUT_DIM 128

// ---------------- scratch (static device globals; no allocation) ----------------
__device__ __half   g_qh[N_NODES * HID];
__device__ __half   g_kh[N_NODES * HID];
__device__ __half   g_vh[N_NODES * HID];
__device__ float    g_s[N_NODES * HID];      // skip (x@Ws+bs), fp32
__device__ float    g_h[N_NODES * HID];      // conv out (pre-LN)
__device__ __half   g_xch[N_NODES * IN_DIM]; // fp16 GEMM A operand
__device__ __half   g_wch[4 * IN_DIM * HID]; // fp16 transposed weights [N,K] x4
__device__ float    g_w[N_EDGES];            // overflow spill for edge weights
__device__ int      g_deg[N_NODES];
__device__ int      g_off[N_NODES + 1];
__device__ int      g_cursor[N_NODES];
__device__ int      g_csrsrc[N_EDGES];
__device__ int      g_src[N_EDGES];
__device__ int      g_dst[N_EDGES];
__device__ float    g_buck[128];             // 64 buckets x (sum, sumsq)
__device__ float    g_stat[2];               // mean, inv_std
__device__ int      g_is64;

// ---------------- edge-index dtype detection ----------------
__global__ void detect_idx_kernel(const long long* __restrict__ ei) {
    int stride = gridDim.x * blockDim.x;
    int bad = 0;
    for (int i = blockIdx.x * blockDim.x + threadIdx.x; i < N_EDGES; i += stride) {
        long long v = ei[i];
        if (v < 0 || v >= N_NODES) bad = 1;
    }
    if (__syncthreads_or(bad) && threadIdx.x == 0) atomicAnd(&g_is64, 0);
}

__global__ void cvt_count_kernel(const void* __restrict__ eiv) {
    const bool is64 = (g_is64 != 0);
    const long long* e64 = (const long long*)eiv;
    const int*       e32 = (const int*)eiv;
    int stride = gridDim.x * blockDim.x;
    for (int e = blockIdx.x * blockDim.x + threadIdx.x; e < N_EDGES; e += stride) {
        long long sv = is64 ? e64[e]           : (long long)e32[e];
        long long dv = is64 ? e64[N_EDGES + e] : (long long)e32[N_EDGES + e];
        int s = (int)sv, d = (int)dv;
        if (s < 0) s = 0; if (s >= N_NODES) s = N_NODES - 1;
        if (d < 0) d = 0; if (d >= N_NODES) d = N_NODES - 1;
        g_src[e] = s;
        g_dst[e] = d;
        atomicAdd(&g_deg[d], 1);
    }
}

__global__ void scan_offsets_kernel() {
    __shared__ int partial[1024];
    int t = threadIdx.x;
    const int C = (N_NODES + 1023) / 1024;
    int lo = t * C;
    int hi = lo + C; if (hi > N_NODES) hi = N_NODES;
    if (lo > N_NODES) lo = N_NODES;
    int s = 0;
    for (int i = lo; i < hi; i++) s += g_deg[i];
    partial[t] = s;
    __syncthreads();
    for (int o = 1; o < 1024; o <<= 1) {
        int add = (t >= o) ? partial[t - o] : 0;
        __syncthreads();
        partial[t] += add;
        __syncthreads();
    }
    int run = partial[t] - s;
    for (int i = lo; i < hi; i++) {
        g_off[i] = run;
        g_cursor[i] = run;
        run += g_deg[i];
    }
    if (t == 1023) g_off[N_NODES] = partial[1023];
}

__global__ void fill_csr_kernel() {
    int stride = gridDim.x * blockDim.x;
    for (int e = blockIdx.x * blockDim.x + threadIdx.x; e < N_EDGES; e += stride) {
        int p = atomicAdd(&g_cursor[g_dst[e]], 1);
        if (p >= 0 && p < N_EDGES) g_csrsrc[p] = g_src[e];
    }
}

// ---------------- fp16 pre-conversion ----------------
__global__ void cvt_f2h_kernel(const float* __restrict__ in, __half* __restrict__ out, int n) {
    int stride = gridDim.x * blockDim.x;
    for (int i = blockIdx.x * blockDim.x + threadIdx.x; i < n; i += stride)
        out[i] = __float2half(in[i]);
}

// 4 weight mats [K,N] -> fp16 transposed [N,K], one launch (blockIdx.y selects)
__global__ void cvtT4_f2h_kernel(const float* __restrict__ W0, const float* __restrict__ W1,
                                 const float* __restrict__ W2, const float* __restrict__ W3,
                                 __half* __restrict__ out, int K, int N) {
    const float* W;
    switch (blockIdx.y) {
        case 0: W = W0; break;
        case 1: W = W1; break;
        case 2: W = W2; break;
        default: W = W3; break;
    }
    __half* o = out + (long)blockIdx.y * K * N;
    int stride = gridDim.x * blockDim.x;
    int total = K * N;
    for (int i = blockIdx.x * blockDim.x + threadIdx.x; i < total; i += stride) {
        int k = i / N, n = i - k * N;
        o[n * K + k] = __float2half(W[i]);
    }
}

// ---------------- fp16 tensor-core GEMM (mma.sync m16n8k16 + ldmatrix) ----------------
__device__ __forceinline__ void mma_f16(float* c, const unsigned* a, const unsigned* b) {
    asm volatile(
        "mma.sync.aligned.m16n8k16.row.col.f32.f16.f16.f32 "
        "{%0,%1,%2,%3}, {%4,%5,%6,%7}, {%8,%9}, {%0,%1,%2,%3};"
        : "+f"(c[0]), "+f"(c[1]), "+f"(c[2]), "+f"(c[3])
        : "r"(a[0]), "r"(a[1]), "r"(a[2]), "r"(a[3]), "r"(b[0]), "r"(b[1]));
}

__device__ __forceinline__ void ldsm_x4(unsigned* r, uint32_t saddr) {
    asm volatile("ldmatrix.sync.aligned.m8n8.x4.shared.b16 {%0,%1,%2,%3}, [%4];"
        : "=r"(r[0]), "=r"(r[1]), "=r"(r[2]), "=r"(r[3]) : "r"(saddr));
}

__device__ __forceinline__ void ldsm_x2(unsigned* r, uint32_t saddr) {
    asm volatile("ldmatrix.sync.aligned.m8n8.x2.shared.b16 {%0,%1}, [%2];"
        : "=r"(r[0]), "=r"(r[1]) : "r"(saddr));
}

__device__ __forceinline__ void cpasync16(void* smem, const void* gmem) {
    unsigned saddr = (unsigned)__cvta_generic_to_shared(smem);
    asm volatile("cp.async.ca.shared.global [%0], [%1], 16;" :: "r"(saddr), "l"(gmem));
}

#define HPAD 40
#define HSTAGES 4
#define GEMM_SMEM_BYTES (HSTAGES * 2 * 128 * HPAD * 2)

template <int NTOT, int K>
__global__ void __launch_bounds__(256, 2)
gemm4_f16_kernel(const __half* __restrict__ A, const __half* __restrict__ BtAll,
                 const float* __restrict__ c0, const float* __restrict__ c1,
                 const float* __restrict__ c2, const float* __restrict__ c3,
                 void* __restrict__ O0, void* __restrict__ O1,
                 void* __restrict__ O2, void* __restrict__ O3, int M) {
    const float* bias; void* Ov;
    switch (blockIdx.z) {
        case 0: bias = c0; Ov = O0; break;
        case 1: bias = c1; Ov = O1; break;
        case 2: bias = c2; Ov = O2; break;
        default: bias = c3; Ov = O3; break;
    }
    const bool halfOut = (blockIdx.z < 3);
    const __half* Bt = BtAll + (long)blockIdx.z * NTOT * K;

    extern __shared__ __half hsm[];
    __half (*As)[128][HPAD] = (__half(*)[128][HPAD])hsm;
    __half (*Bs)[128][HPAD] = (__half(*)[128][HPAD])(hsm + HSTAGES * 128 * HPAD);

    int tid = threadIdx.x;
    int lane = tid & 31;
    int wid = tid >> 5;
    int wr = wid >> 2;
    int wc = wid & 3;
    int grp = lane >> 2;
    int qid = lane & 3;
    int bm = blockIdx.x * 128;
    int bn = blockIdx.y * 128;

    float acc[4][4][4];
#pragma unroll
    for (int i = 0; i < 4; i++)
#pragma unroll
        for (int j = 0; j < 4; j++)
#pragma unroll
            for (int r = 0; r < 4; r++) acc[i][j][r] = 0.f;

    int r0i = tid >> 2,          c0i = (tid & 3) * 8;
    int r1i = (tid + 256) >> 2,  c1i = (tid & 3) * 8;
    int a_g0 = bm + r0i; if (a_g0 >= M) a_g0 = M - 1;
    int a_g1 = bm + r1i; if (a_g1 >= M) a_g1 = M - 1;
    int b_g0 = bn + r0i, b_g1 = bn + r1i;

    int a_lrow = wr * 64 + (lane & 15);
    int a_lk   = 8 * (lane >> 4);
    int b_lcol = wc * 32 + (lane & 7);
    int b_lk   = 8 * ((lane >> 3) & 1);

    const int KT = K / 32;

#define PREFETCH(st, kt_) do { \
        int kb_ = (kt_) * 32; \
        cpasync16(&As[st][r0i][c0i], A + (long)a_g0 * K + kb_ + c0i); \
        cpasync16(&As[st][r1i][c1i], A + (long)a_g1 * K + kb_ + c1i); \
        cpasync16(&Bs[st][r0i][c0i], Bt + (long)b_g0 * K + kb_ + c0i); \
        cpasync16(&Bs[st][r1i][c1i], Bt + (long)b_g1 * K + kb_ + c1i); \
        asm volatile("cp.async.commit_group;"); \
    } while (0)

    for (int st = 0; st < 3 && st < KT; st++) PREFETCH(st, st);

    for (int kt = 0; kt < KT; kt++) {
        int rem = KT - 1 - kt;
        if (rem >= 2)      asm volatile("cp.async.wait_group 2;");
        else if (rem == 1) asm volatile("cp.async.wait_group 1;");
        else               asm volatile("cp.async.wait_group 0;");
        __syncthreads();
        if (kt + 3 < KT) PREFETCH((kt + 3) & 3, kt + 3);
        int buf = kt & 3;

        uint32_t asb = (uint32_t)__cvta_generic_to_shared(&As[buf][0][0]);
        uint32_t bsb = (uint32_t)__cvta_generic_to_shared(&Bs[buf][0][0]);

#pragma unroll
        for (int ks = 0; ks < 32; ks += 16) {
            unsigned afr[4][4];
#pragma unroll
            for (int mi = 0; mi < 4; mi++)
                ldsm_x4(afr[mi], asb + ((a_lrow + mi * 16) * HPAD + ks + a_lk) * 2);
            unsigned bfr[4][2];
#pragma unroll
            for (int ni = 0; ni < 4; ni++)
                ldsm_x2(bfr[ni], bsb + ((b_lcol + ni * 8) * HPAD + ks + b_lk) * 2);
#pragma unroll
            for (int mi = 0; mi < 4; mi++)
#pragma unroll
                for (int ni = 0; ni < 4; ni++)
                    mma_f16(acc[mi][ni], afr[mi], bfr[ni]);
        }
        __syncthreads();
    }
#undef PREFETCH

#pragma unroll
    for (int mi = 0; mi < 4; mi++) {
        int r0 = bm + wr * 64 + mi * 16 + grp;
#pragma unroll
        for (int ni = 0; ni < 4; ni++) {
            int gc = bn + wc * 32 + ni * 8 + 2 * qid;
            float bz0 = bias[gc], bz1 = bias[gc + 1];
            if (halfOut) {
                __half* Oh = (__half*)Ov;
                if (r0 < M)
                    *(__half2*)&Oh[(long)r0 * NTOT + gc] =
                        __floats2half2_rn(acc[mi][ni][0] + bz0, acc[mi][ni][1] + bz1);
                if (r0 + 8 < M)
                    *(__half2*)&Oh[(long)(r0 + 8) * NTOT + gc] =
                        __floats2half2_rn(acc[mi][ni][2] + bz0, acc[mi][ni][3] + bz1);
            } else {
                float* Of = (float*)Ov;
                if (r0 < M) {
                    Of[(long)r0 * NTOT + gc]     = acc[mi][ni][0] + bz0;
                    Of[(long)r0 * NTOT + gc + 1] = acc[mi][ni][1] + bz1;
                }
                if (r0 + 8 < M) {
                    Of[(long)(r0 + 8) * NTOT + gc]     = acc[mi][ni][2] + bz0;
                    Of[(long)(r0 + 8) * NTOT + gc + 1] = acc[mi][ni][3] + bz1;
                }
            }
        }
    }
}

// ---------------- fused edge kernel: scores + softmax + aggregate + LN stats ----------------
// One block per node. Caches edge (src, weight) in smem up to MAXE; spills to g_w beyond.
template <int D, int WARPS, int MAXE>
__global__ void __launch_bounds__(WARPS * 32)
edge_fused_kernel(const __half* __restrict__ q, const __half* __restrict__ k,
                  const __half* __restrict__ v, const float* __restrict__ skip,
                  float* __restrict__ out, float scale) {
    int n = blockIdx.x;
    __shared__ __half2 qs[D / 2];
    __shared__ float wsh[MAXE];
    __shared__ int   ssh[MAXE];
    __shared__ float red[WARPS], red2[WARPS];
    __shared__ float bc_m, bc_inv;
    int tid = threadIdx.x, lane = tid & 31, wid = tid >> 5;
    int s0 = g_off[n], s1 = g_off[n + 1], deg = s1 - s0;

    const __half2* q2 = (const __half2*)(q + (long)n * D);
    for (int i = tid; i < D / 2; i += WARPS * 32) qs[i] = q2[i];
    __syncthreads();

    // phase A: scores (warp per edge)
    float lmax = -3.4e38f;
    for (int j = s0 + wid; j < s1; j += WARPS) {
        int src = g_csrsrc[j];
        const __half2* kr = (const __half2*)(k + (long)src * D);
        float acc = 0.f;
#pragma unroll
        for (int i = 0; i < D / 64; i++) {
            float2 a = __half22float2(qs[lane + 32 * i]);
            float2 b = __half22float2(kr[lane + 32 * i]);
            acc += a.x * b.x + a.y * b.y;
        }
#pragma unroll
        for (int o = 16; o > 0; o >>= 1) acc += __shfl_xor_sync(0xffffffffu, acc, o);
        float sc = acc * scale;
        int loc = j - s0;
        if (lane == 0) {
            if (loc < MAXE) { wsh[loc] = sc; ssh[loc] = src; }
            else            g_w[j] = sc;
        }
        lmax = fmaxf(lmax, sc);
    }
    if (lane == 0) red[wid] = lmax;
    __syncthreads();
    if (tid == 0) {
        float m = red[0];
#pragma unroll
        for (int i = 1; i < WARPS; i++) m = fmaxf(m, red[i]);
        bc_m = m;
    }
    __syncthreads();
    float m = bc_m;

    // phase B: exp + sum
    float lsum = 0.f;
    for (int loc = tid; loc < deg; loc += WARPS * 32) {
        float sc = (loc < MAXE) ? wsh[loc] : g_w[s0 + loc];
        float w = __expf(sc - m);
        if (loc < MAXE) wsh[loc] = w; else g_w[s0 + loc] = w;
        lsum += w;
    }
#pragma unroll
    for (int o = 16; o > 0; o >>= 1) lsum += __shfl_xor_sync(0xffffffffu, lsum, o);
    if (lane == 0) red[wid] = lsum;
    __syncthreads();
    if (tid == 0) {
        float sum = 0.f;
#pragma unroll
        for (int i = 0; i < WARPS; i++) sum += red[i];
        bc_inv = (sum > 0.f) ? 1.f / sum : 0.f;
    }
    __syncthreads();
    float inv = bc_inv;

    // phase C: aggregate (first D/2 threads own half2 channels) + LN stat partials
    float sloc = 0.f, s2loc = 0.f;
    if (tid < D / 2) {
        float ax = 0.f, ay = 0.f;
        const __half2* v2 = (const __half2*)v;
        for (int loc = 0; loc < deg; loc++) {
            int src  = (loc < MAXE) ? ssh[loc] : g_csrsrc[s0 + loc];
            float we = (loc < MAXE) ? wsh[loc] : g_w[s0 + loc];
            float2 vv = __half22float2(v2[(long)src * (D / 2) + tid]);
            ax += we * vv.x;
            ay += we * vv.y;
        }
        long base = (long)n * D + 2 * tid;
        float h0 = skip[base]     + ax * inv;
        float h1 = skip[base + 1] + ay * inv;
        out[base]     = h0;
        out[base + 1] = h1;
        sloc  = h0 + h1;
        s2loc = h0 * h0 + h1 * h1;
    }
#pragma unroll
    for (int o = 16; o > 0; o >>= 1) {
        sloc  += __shfl_xor_sync(0xffffffffu, sloc, o);
        s2loc += __shfl_xor_sync(0xffffffffu, s2loc, o);
    }
    if (lane == 0) { red[wid] = sloc; red2[wid] = s2loc; }
    __syncthreads();
    if (tid == 0) {
        float ts = 0.f, ts2 = 0.f;
#pragma unroll
        for (int i = 0; i < WARPS; i++) { ts += red[i]; ts2 += red2[i]; }
        int b = (n & 63) * 2;
        atomicAdd(&g_buck[b], ts);
        atomicAdd(&g_buck[b + 1], ts2);
    }
}

// ---------------- LN stat finalize + normalize ----------------
__global__ void finalize_stats_kernel(float M) {
    int t = threadIdx.x;   // 64 threads
    float s = g_buck[t * 2], s2 = g_buck[t * 2 + 1];
#pragma unroll
    for (int o = 16; o > 0; o >>= 1) {
        s  += __shfl_xor_sync(0xffffffffu, s, o);
        s2 += __shfl_xor_sync(0xffffffffu, s2, o);
    }
    __shared__ float sh[2][2];
    if ((t & 31) == 0) { sh[0][t >> 5] = s; sh[1][t >> 5] = s2; }
    __syncthreads();
    if (t == 0) {
        float S = sh[0][0] + sh[0][1], S2 = sh[1][0] + sh[1][1];
        float mean = S / M;
        float var = S2 / M - mean * mean;
        if (var < 0.f) var = 0.f;
        g_stat[0] = mean;
        g_stat[1] = 1.0f / (sqrtf(var) + 1e-5f);
    }
}

__global__ void normalize_elu_h_kernel(const float* __restrict__ h,
                                       const float* __restrict__ gamma,
                                       const float* __restrict__ beta,
                                       __half* __restrict__ out,
                                       int dmask, long M) {
    float fm = g_stat[0], inv = g_stat[1];
    long stride = (long)gridDim.x * blockDim.x;
    for (long i = (long)blockIdx.x * blockDim.x + threadIdx.x; i < M; i += stride) {
        int c = (int)(i & dmask);
        float y = (h[i] - fm) * inv * gamma[c] + beta[c];
        y = (y > 0.f) ? y : expm1f(y);
        out[i] = __float2half(y);
    }
}

__global__ void normalize_f_kernel(const float* __restrict__ h,
                                   const float* __restrict__ gamma,
                                   const float* __restrict__ beta,
                                   float* __restrict__ out,
                                   int dmask, long M) {
    float fm = g_stat[0], inv = g_stat[1];
    long stride = (long)gridDim.x * blockDim.x;
    for (long i = (long)blockIdx.x * blockDim.x + threadIdx.x; i < M; i += stride) {
        int c = (int)(i & dmask);
        out[i] = (h[i] - fm) * inv * gamma[c] + beta[c];
    }
}

// ---------------- host launcher ----------------
extern "C" void kernel_launch(void* const* d_in, const int* in_sizes, int n_in,
                              void* d_out, int out_size) {
    const float* x    = (const float*)d_in[0];
    const float* Wq1  = (const float*)d_in[1];
    const float* bq1  = (const float*)d_in[2];
    const float* Wk1  = (const float*)d_in[3];
    const float* bk1  = (const float*)d_in[4];
    const float* Wv1  = (const float*)d_in[5];
    const float* bv1  = (const float*)d_in[6];
    const float* Ws1  = (const float*)d_in[7];
    const float* bs1  = (const float*)d_in[8];
    const float* ga1  = (const float*)d_in[9];
    const float* be1  = (const float*)d_in[10];
    const float* Wq2  = (const float*)d_in[11];
    const float* bq2  = (const float*)d_in[12];
    const float* Wk2  = (const float*)d_in[13];
    const float* bk2  = (const float*)d_in[14];
    const float* Wv2  = (const float*)d_in[15];
    const float* bv2  = (const float*)d_in[16];
    const float* Ws2  = (const float*)d_in[17];
    const float* bs2  = (const float*)d_in[18];
    const float* ga2  = (const float*)d_in[19];
    const float* be2  = (const float*)d_in[20];
    const void*  ei   = d_in[21];
    float* out = (float*)d_out;

    void *p_qh, *p_kh, *p_vh, *p_s, *p_h, *p_xch, *p_wch, *p_deg, *p_buck, *p_is64;
    cudaGetSymbolAddress(&p_qh, g_qh);
    cudaGetSymbolAddress(&p_kh, g_kh);
    cudaGetSymbolAddress(&p_vh, g_vh);
    cudaGetSymbolAddress(&p_s, g_s);
    cudaGetSymbolAddress(&p_h, g_h);
    cudaGetSymbolAddress(&p_xch, g_xch);
    cudaGetSymbolAddress(&p_wch, g_wch);
    cudaGetSymbolAddress(&p_deg, g_deg);
    cudaGetSymbolAddress(&p_buck, g_buck);
    cudaGetSymbolAddress(&p_is64, g_is64);

    __half* qh = (__half*)p_qh;
    __half* kh = (__half*)p_kh;
    __half* vh = (__half*)p_vh;
    float*  s  = (float*)p_s;
    float*  h  = (float*)p_h;
    __half* xh = (__half*)p_xch;
    __half* wh = (__half*)p_wch;

    cudaFuncSetAttribute(gemm4_f16_kernel<HID, IN_DIM>,
                         cudaFuncAttributeMaxDynamicSharedMemorySize, GEMM_SMEM_BYTES);
    cudaFuncSetAttribute(gemm4_f16_kernel<OUT_DIM, HID>,
                         cudaFuncAttributeMaxDynamicSharedMemorySize, GEMM_SMEM_BYTES);

    // ---- edge dtype detection + CSR build ----
    cudaMemsetAsync(p_is64, 0xFF, sizeof(int), 0);
    detect_idx_kernel<<<1024, 256>>>((const long long*)ei);
    cudaMemsetAsync(p_deg, 0, N_NODES * sizeof(int), 0);
    cvt_count_kernel<<<2048, 256>>>(ei);
    scan_offsets_kernel<<<1, 1024>>>();
    fill_csr_kernel<<<2048, 256>>>();

    // ---- layer 1 ----
    const int W1 = IN_DIM * HID;
    cvt_f2h_kernel<<<2048, 256>>>(x, xh, N_NODES * IN_DIM);
    {
        dim3 g(256, 4);
        cvtT4_f2h_kernel<<<g, 256>>>(Wq1, Wk1, Wv1, Ws1, wh, IN_DIM, HID);
    }
    {
        dim3 grid((N_NODES + 127) / 128, HID / 128, 4);
        gemm4_f16_kernel<HID, IN_DIM><<<grid, 256, GEMM_SMEM_BYTES>>>(
            xh, wh, bq1, bk1, bv1, bs1, qh, kh, vh, s, N_NODES);
    }
    cudaMemsetAsync(p_buck, 0, 128 * sizeof(float), 0);
    edge_fused_kernel<HID, 8, 64><<<N_NODES, 256>>>(qh, kh, vh, s, h, 1.0f / 16.0f);
    finalize_stats_kernel<<<1, 64>>>((float)((long)N_NODES * HID));
    normalize_elu_h_kernel<<<2048, 256>>>(h, ga1, be1, xh, HID - 1, (long)N_NODES * HID);

    // ---- layer 2 ----
    {
        dim3 g(128, 4);
        cvtT4_f2h_kernel<<<g, 256>>>(Wq2, Wk2, Wv2, Ws2, wh, HID, OUT_DIM);
    }
    {
        dim3 grid((N_NODES + 127) / 128, OUT_DIM / 128, 4);
        gemm4_f16_kernel<OUT_DIM, HID><<<grid, 256, GEMM_SMEM_BYTES>>>(
            xh, wh, bq2, bk2, bv2, bs2, qh, kh, vh, s, N_NODES);
    }
    cudaMemsetAsync(p_buck, 0, 128 * sizeof(float), 0);
    edge_fused_kernel<OUT_DIM, 4, 64><<<N_NODES, 128>>>(qh, kh, vh, s, h, 0.08838834764831845f);
    finalize_stats_kernel<<<1, 64>>>((float)((long)N_NODES * OUT_DIM));
    normalize_f_kernel<<<2048, 256>>>(h, ga2, be2, out, OUT_DIM - 1, (long)N_NODES * OUT_DIM);
}

// round 13
// speedup vs baseline: 3.3887x; 1.1333x over previous
#include <cuda_runtime.h>
#include <cuda_fp16.h>
#include <math.h>
#include <stdint.h>

#define N_NODES 50000
#define N_EDGES 800000
#define IN_DIM  512
#define HID     256
#define OUT_DIM 128

// ---------------- scratch (static device globals; no allocation) ----------------
__device__ __half   g_qh[N_NODES * HID];
__device__ __half   g_kh[N_NODES * HID];
__device__ __half   g_vh[N_NODES * HID];
__device__ float    g_s[N_NODES * HID];      // skip (x@Ws+bs), fp32
__device__ float    g_h[N_NODES * HID];      // conv out (pre-LN)
__device__ __half   g_xch[N_NODES * IN_DIM]; // fp16 GEMM A operand
__device__ __half   g_wch[4 * IN_DIM * HID]; // fp16 transposed weights L1
__device__ __half   g_wch2[4 * HID * OUT_DIM]; // fp16 transposed weights L2
__device__ float    g_w[N_EDGES];            // overflow spill for edge weights
__device__ int      g_deg[N_NODES];
__device__ int      g_off[N_NODES + 1];
__device__ int      g_cursor[N_NODES];
__device__ int      g_csrsrc[N_EDGES];
__device__ int      g_src[N_EDGES];
__device__ int      g_dst[N_EDGES];
__device__ float    g_buck[256];             // 2 layers x 64 buckets x (sum,sumsq)
__device__ int      g_is64;

// ---------------- edge-index dtype detection ----------------
__global__ void detect_idx_kernel(const long long* __restrict__ ei) {
    int stride = gridDim.x * blockDim.x;
    int bad = 0;
    for (int i = blockIdx.x * blockDim.x + threadIdx.x; i < N_EDGES; i += stride) {
        long long v = ei[i];
        if (v < 0 || v >= N_NODES) bad = 1;
    }
    if (__syncthreads_or(bad) && threadIdx.x == 0) atomicAnd(&g_is64, 0);
}

__global__ void cvt_count_kernel(const void* __restrict__ eiv) {
    const bool is64 = (g_is64 != 0);
    const long long* e64 = (const long long*)eiv;
    const int*       e32 = (const int*)eiv;
    int stride = gridDim.x * blockDim.x;
    for (int e = blockIdx.x * blockDim.x + threadIdx.x; e < N_EDGES; e += stride) {
        long long sv = is64 ? e64[e]           : (long long)e32[e];
        long long dv = is64 ? e64[N_EDGES + e] : (long long)e32[N_EDGES + e];
        int s = (int)sv, d = (int)dv;
        if (s < 0) s = 0; if (s >= N_NODES) s = N_NODES - 1;
        if (d < 0) d = 0; if (d >= N_NODES) d = N_NODES - 1;
        g_src[e] = s;
        g_dst[e] = d;
        atomicAdd(&g_deg[d], 1);
    }
}

__global__ void scan_offsets_kernel() {
    __shared__ int partial[1024];
    int t = threadIdx.x;
    const int C = (N_NODES + 1023) / 1024;
    int lo = t * C;
    int hi = lo + C; if (hi > N_NODES) hi = N_NODES;
    if (lo > N_NODES) lo = N_NODES;
    int s = 0;
    for (int i = lo; i < hi; i++) s += g_deg[i];
    partial[t] = s;
    __syncthreads();
    for (int o = 1; o < 1024; o <<= 1) {
        int add = (t >= o) ? partial[t - o] : 0;
        __syncthreads();
        partial[t] += add;
        __syncthreads();
    }
    int run = partial[t] - s;
    for (int i = lo; i < hi; i++) {
        g_off[i] = run;
        g_cursor[i] = run;
        run += g_deg[i];
    }
    if (t == 1023) g_off[N_NODES] = partial[1023];
}

__global__ void fill_csr_kernel() {
    int stride = gridDim.x * blockDim.x;
    for (int e = blockIdx.x * blockDim.x + threadIdx.x; e < N_EDGES; e += stride) {
        int p = atomicAdd(&g_cursor[g_dst[e]], 1);
        if (p >= 0 && p < N_EDGES) g_csrsrc[p] = g_src[e];
    }
}

// ---------------- fp16 pre-conversion ----------------
__global__ void cvt_f2h_kernel(const float* __restrict__ in, __half* __restrict__ out, int n) {
    int stride = gridDim.x * blockDim.x;
    for (int i = blockIdx.x * blockDim.x + threadIdx.x; i < n; i += stride)
        out[i] = __float2half(in[i]);
}

__global__ void cvtT4_f2h_kernel(const float* __restrict__ W0, const float* __restrict__ W1,
                                 const float* __restrict__ W2, const float* __restrict__ W3,
                                 __half* __restrict__ out, int K, int N) {
    const float* W;
    switch (blockIdx.y) {
        case 0: W = W0; break;
        case 1: W = W1; break;
        case 2: W = W2; break;
        default: W = W3; break;
    }
    __half* o = out + (long)blockIdx.y * K * N;
    int stride = gridDim.x * blockDim.x;
    int total = K * N;
    for (int i = blockIdx.x * blockDim.x + threadIdx.x; i < total; i += stride) {
        int k = i / N, n = i - k * N;
        o[n * K + k] = __float2half(W[i]);
    }
}

// ---------------- fp16 tensor-core GEMM (mma.sync m16n8k16 + ldmatrix) ----------------
__device__ __forceinline__ void mma_f16(float* c, const unsigned* a, const unsigned* b) {
    asm volatile(
        "mma.sync.aligned.m16n8k16.row.col.f32.f16.f16.f32 "
        "{%0,%1,%2,%3}, {%4,%5,%6,%7}, {%8,%9}, {%0,%1,%2,%3};"
        : "+f"(c[0]), "+f"(c[1]), "+f"(c[2]), "+f"(c[3])
        : "r"(a[0]), "r"(a[1]), "r"(a[2]), "r"(a[3]), "r"(b[0]), "r"(b[1]));
}

__device__ __forceinline__ void ldsm_x4(unsigned* r, uint32_t saddr) {
    asm volatile("ldmatrix.sync.aligned.m8n8.x4.shared.b16 {%0,%1,%2,%3}, [%4];"
        : "=r"(r[0]), "=r"(r[1]), "=r"(r[2]), "=r"(r[3]) : "r"(saddr));
}

__device__ __forceinline__ void ldsm_x2(unsigned* r, uint32_t saddr) {
    asm volatile("ldmatrix.sync.aligned.m8n8.x2.shared.b16 {%0,%1}, [%2];"
        : "=r"(r[0]), "=r"(r[1]) : "r"(saddr));
}

__device__ __forceinline__ void cpasync16(void* smem, const void* gmem) {
    unsigned saddr = (unsigned)__cvta_generic_to_shared(smem);
    asm volatile("cp.async.ca.shared.global [%0], [%1], 16;" :: "r"(saddr), "l"(gmem));
}

#define HPAD 40
#define HSTAGES 4
#define GEMM_SMEM_BYTES (HSTAGES * 2 * 128 * HPAD * 2)

template <int NTOT, int K>
__global__ void __launch_bounds__(256, 2)
gemm4_f16_kernel(const __half* __restrict__ A, const __half* __restrict__ BtAll,
                 const float* __restrict__ c0, const float* __restrict__ c1,
                 const float* __restrict__ c2, const float* __restrict__ c3,
                 void* __restrict__ O0, void* __restrict__ O1,
                 void* __restrict__ O2, void* __restrict__ O3, int M) {
    const float* bias; void* Ov;
    switch (blockIdx.z) {
        case 0: bias = c0; Ov = O0; break;
        case 1: bias = c1; Ov = O1; break;
        case 2: bias = c2; Ov = O2; break;
        default: bias = c3; Ov = O3; break;
    }
    const bool halfOut = (blockIdx.z < 3);
    const __half* Bt = BtAll + (long)blockIdx.z * NTOT * K;

    extern __shared__ __half hsm[];
    __half (*As)[128][HPAD] = (__half(*)[128][HPAD])hsm;
    __half (*Bs)[128][HPAD] = (__half(*)[128][HPAD])(hsm + HSTAGES * 128 * HPAD);

    int tid = threadIdx.x;
    int lane = tid & 31;
    int wid = tid >> 5;
    int wr = wid >> 2;
    int wc = wid & 3;
    int grp = lane >> 2;
    int qid = lane & 3;
    int bm = blockIdx.x * 128;
    int bn = blockIdx.y * 128;

    float acc[4][4][4];
#pragma unroll
    for (int i = 0; i < 4; i++)
#pragma unroll
        for (int j = 0; j < 4; j++)
#pragma unroll
            for (int r = 0; r < 4; r++) acc[i][j][r] = 0.f;

    int r0i = tid >> 2,          c0i = (tid & 3) * 8;
    int r1i = (tid + 256) >> 2,  c1i = (tid & 3) * 8;
    int a_g0 = bm + r0i; if (a_g0 >= M) a_g0 = M - 1;
    int a_g1 = bm + r1i; if (a_g1 >= M) a_g1 = M - 1;
    int b_g0 = bn + r0i, b_g1 = bn + r1i;

    int a_lrow = wr * 64 + (lane & 15);
    int a_lk   = 8 * (lane >> 4);
    int b_lcol = wc * 32 + (lane & 7);
    int b_lk   = 8 * ((lane >> 3) & 1);

    const int KT = K / 32;

#define PREFETCH(st, kt_) do { \
        int kb_ = (kt_) * 32; \
        cpasync16(&As[st][r0i][c0i], A + (long)a_g0 * K + kb_ + c0i); \
        cpasync16(&As[st][r1i][c1i], A + (long)a_g1 * K + kb_ + c1i); \
        cpasync16(&Bs[st][r0i][c0i], Bt + (long)b_g0 * K + kb_ + c0i); \
        cpasync16(&Bs[st][r1i][c1i], Bt + (long)b_g1 * K + kb_ + c1i); \
        asm volatile("cp.async.commit_group;"); \
    } while (0)

    for (int st = 0; st < 3 && st < KT; st++) PREFETCH(st, st);

    for (int kt = 0; kt < KT; kt++) {
        int rem = KT - 1 - kt;
        if (rem >= 2)      asm volatile("cp.async.wait_group 2;");
        else if (rem == 1) asm volatile("cp.async.wait_group 1;");
        else               asm volatile("cp.async.wait_group 0;");
        __syncthreads();
        if (kt + 3 < KT) PREFETCH((kt + 3) & 3, kt + 3);
        int buf = kt & 3;

        uint32_t asb = (uint32_t)__cvta_generic_to_shared(&As[buf][0][0]);
        uint32_t bsb = (uint32_t)__cvta_generic_to_shared(&Bs[buf][0][0]);

#pragma unroll
        for (int ks = 0; ks < 32; ks += 16) {
            unsigned afr[4][4];
#pragma unroll
            for (int mi = 0; mi < 4; mi++)
                ldsm_x4(afr[mi], asb + ((a_lrow + mi * 16) * HPAD + ks + a_lk) * 2);
            unsigned bfr[4][2];
#pragma unroll
            for (int ni = 0; ni < 4; ni++)
                ldsm_x2(bfr[ni], bsb + ((b_lcol + ni * 8) * HPAD + ks + b_lk) * 2);
#pragma unroll
            for (int mi = 0; mi < 4; mi++)
#pragma unroll
                for (int ni = 0; ni < 4; ni++)
                    mma_f16(acc[mi][ni], afr[mi], bfr[ni]);
        }
        __syncthreads();
    }
#undef PREFETCH

#pragma unroll
    for (int mi = 0; mi < 4; mi++) {
        int r0 = bm + wr * 64 + mi * 16 + grp;
#pragma unroll
        for (int ni = 0; ni < 4; ni++) {
            int gc = bn + wc * 32 + ni * 8 + 2 * qid;
            float bz0 = bias[gc], bz1 = bias[gc + 1];
            if (halfOut) {
                __half* Oh = (__half*)Ov;
                if (r0 < M)
                    *(__half2*)&Oh[(long)r0 * NTOT + gc] =
                        __floats2half2_rn(acc[mi][ni][0] + bz0, acc[mi][ni][1] + bz1);
                if (r0 + 8 < M)
                    *(__half2*)&Oh[(long)(r0 + 8) * NTOT + gc] =
                        __floats2half2_rn(acc[mi][ni][2] + bz0, acc[mi][ni][3] + bz1);
            } else {
                float* Of = (float*)Ov;
                if (r0 < M) {
                    Of[(long)r0 * NTOT + gc]     = acc[mi][ni][0] + bz0;
                    Of[(long)r0 * NTOT + gc + 1] = acc[mi][ni][1] + bz1;
                }
                if (r0 + 8 < M) {
                    Of[(long)(r0 + 8) * NTOT + gc]     = acc[mi][ni][2] + bz0;
                    Of[(long)(r0 + 8) * NTOT + gc + 1] = acc[mi][ni][3] + bz1;
                }
            }
        }
    }
}

// ---------------- fused edge kernel: scores + softmax + aggregate + LN stats ----------------
template <int D, int WARPS, int MAXE>
__global__ void __launch_bounds__(WARPS * 32)
edge_fused_kernel(const __half* __restrict__ q, const __half* __restrict__ k,
                  const __half* __restrict__ v, const float* __restrict__ skip,
                  float* __restrict__ out, float* __restrict__ buck, float scale) {
    int n = blockIdx.x;
    __shared__ __half2 qs[D / 2];
    __shared__ float wsh[MAXE];
    __shared__ int   ssh[MAXE];
    __shared__ float red[WARPS], red2[WARPS];
    __shared__ float bc_m, bc_inv;
    int tid = threadIdx.x, lane = tid & 31, wid = tid >> 5;
    int s0 = g_off[n], s1 = g_off[n + 1], deg = s1 - s0;

    const __half2* q2 = (const __half2*)(q + (long)n * D);
    for (int i = tid; i < D / 2; i += WARPS * 32) qs[i] = q2[i];
    __syncthreads();

    float lmax = -3.4e38f;
    for (int j = s0 + wid; j < s1; j += WARPS) {
        int src = g_csrsrc[j];
        const __half2* kr = (const __half2*)(k + (long)src * D);
        float acc = 0.f;
#pragma unroll
        for (int i = 0; i < D / 64; i++) {
            float2 a = __half22float2(qs[lane + 32 * i]);
            float2 b = __half22float2(kr[lane + 32 * i]);
            acc += a.x * b.x + a.y * b.y;
        }
#pragma unroll
        for (int o = 16; o > 0; o >>= 1) acc += __shfl_xor_sync(0xffffffffu, acc, o);
        float sc = acc * scale;
        int loc = j - s0;
        if (lane == 0) {
            if (loc < MAXE) { wsh[loc] = sc; ssh[loc] = src; }
            else            g_w[j] = sc;
        }
        lmax = fmaxf(lmax, sc);
    }
    if (lane == 0) red[wid] = lmax;
    __syncthreads();
    if (tid == 0) {
        float m = red[0];
#pragma unroll
        for (int i = 1; i < WARPS; i++) m = fmaxf(m, red[i]);
        bc_m = m;
    }
    __syncthreads();
    float m = bc_m;

    float lsum = 0.f;
    for (int loc = tid; loc < deg; loc += WARPS * 32) {
        float sc = (loc < MAXE) ? wsh[loc] : g_w[s0 + loc];
        float w = __expf(sc - m);
        if (loc < MAXE) wsh[loc] = w; else g_w[s0 + loc] = w;
        lsum += w;
    }
#pragma unroll
    for (int o = 16; o > 0; o >>= 1) lsum += __shfl_xor_sync(0xffffffffu, lsum, o);
    if (lane == 0) red[wid] = lsum;
    __syncthreads();
    if (tid == 0) {
        float sum = 0.f;
#pragma unroll
        for (int i = 0; i < WARPS; i++) sum += red[i];
        bc_inv = (sum > 0.f) ? 1.f / sum : 0.f;
    }
    __syncthreads();
    float inv = bc_inv;

    float sloc = 0.f, s2loc = 0.f;
    if (tid < D / 2) {
        float ax = 0.f, ay = 0.f;
        const __half2* v2 = (const __half2*)v;
        for (int loc = 0; loc < deg; loc++) {
            int src  = (loc < MAXE) ? ssh[loc] : g_csrsrc[s0 + loc];
            float we = (loc < MAXE) ? wsh[loc] : g_w[s0 + loc];
            float2 vv = __half22float2(v2[(long)src * (D / 2) + tid]);
            ax += we * vv.x;
            ay += we * vv.y;
        }
        long base = (long)n * D + 2 * tid;
        float h0 = skip[base]     + ax * inv;
        float h1 = skip[base + 1] + ay * inv;
        out[base]     = h0;
        out[base + 1] = h1;
        sloc  = h0 + h1;
        s2loc = h0 * h0 + h1 * h1;
    }
#pragma unroll
    for (int o = 16; o > 0; o >>= 1) {
        sloc  += __shfl_xor_sync(0xffffffffu, sloc, o);
        s2loc += __shfl_xor_sync(0xffffffffu, s2loc, o);
    }
    if (lane == 0) { red[wid] = sloc; red2[wid] = s2loc; }
    __syncthreads();
    if (tid == 0) {
        float ts = 0.f, ts2 = 0.f;
#pragma unroll
        for (int i = 0; i < WARPS; i++) { ts += red[i]; ts2 += red2[i]; }
        int b = (n & 63) * 2;
        atomicAdd(&buck[b], ts);
        atomicAdd(&buck[b + 1], ts2);
    }
}

// ---------------- normalize (stats computed in-block from buckets) ----------------
__device__ __forceinline__ void block_stats(const float* __restrict__ buck, float M,
                                            float& fm, float& inv) {
    __shared__ float sh[2];
    if (threadIdx.x < 32) {
        int l = threadIdx.x;
        float s  = buck[2 * l]     + buck[2 * (l + 32)];
        float s2 = buck[2 * l + 1] + buck[2 * (l + 32) + 1];
#pragma unroll
        for (int o = 16; o > 0; o >>= 1) {
            s  += __shfl_xor_sync(0xffffffffu, s, o);
            s2 += __shfl_xor_sync(0xffffffffu, s2, o);
        }
        if (l == 0) {
            float mean = s / M;
            float var = s2 / M - mean * mean;
            if (var < 0.f) var = 0.f;
            sh[0] = mean;
            sh[1] = 1.0f / (sqrtf(var) + 1e-5f);
        }
    }
    __syncthreads();
    fm = sh[0];
    inv = sh[1];
}

__global__ void normalize_elu_h_kernel(const float* __restrict__ h,
                                       const float* __restrict__ gamma,
                                       const float* __restrict__ beta,
                                       __half* __restrict__ out,
                                       const float* __restrict__ buck,
                                       int dmask, long M) {
    float fm, inv;
    block_stats(buck, (float)M, fm, inv);
    long stride = (long)gridDim.x * blockDim.x;
    for (long i = (long)blockIdx.x * blockDim.x + threadIdx.x; i < M; i += stride) {
        int c = (int)(i & dmask);
        float y = (h[i] - fm) * inv * gamma[c] + beta[c];
        y = (y > 0.f) ? y : expm1f(y);
        out[i] = __float2half(y);
    }
}

__global__ void normalize_f_kernel(const float* __restrict__ h,
                                   const float* __restrict__ gamma,
                                   const float* __restrict__ beta,
                                   float* __restrict__ out,
                                   const float* __restrict__ buck,
                                   int dmask, long M) {
    float fm, inv;
    block_stats(buck, (float)M, fm, inv);
    long stride = (long)gridDim.x * blockDim.x;
    for (long i = (long)blockIdx.x * blockDim.x + threadIdx.x; i < M; i += stride) {
        int c = (int)(i & dmask);
        out[i] = (h[i] - fm) * inv * gamma[c] + beta[c];
    }
}

// ---------------- host launcher ----------------
extern "C" void kernel_launch(void* const* d_in, const int* in_sizes, int n_in,
                              void* d_out, int out_size) {
    const float* x    = (const float*)d_in[0];
    const float* Wq1  = (const float*)d_in[1];
    const float* bq1  = (const float*)d_in[2];
    const float* Wk1  = (const float*)d_in[3];
    const float* bk1  = (const float*)d_in[4];
    const float* Wv1  = (const float*)d_in[5];
    const float* bv1  = (const float*)d_in[6];
    const float* Ws1  = (const float*)d_in[7];
    const float* bs1  = (const float*)d_in[8];
    const float* ga1  = (const float*)d_in[9];
    const float* be1  = (const float*)d_in[10];
    const float* Wq2  = (const float*)d_in[11];
    const float* bq2  = (const float*)d_in[12];
    const float* Wk2  = (const float*)d_in[13];
    const float* bk2  = (const float*)d_in[14];
    const float* Wv2  = (const float*)d_in[15];
    const float* bv2  = (const float*)d_in[16];
    const float* Ws2  = (const float*)d_in[17];
    const float* bs2  = (const float*)d_in[18];
    const float* ga2  = (const float*)d_in[19];
    const float* be2  = (const float*)d_in[20];
    const void*  ei   = d_in[21];
    float* out = (float*)d_out;

    void *p_qh, *p_kh, *p_vh, *p_s, *p_h, *p_xch, *p_wch, *p_wch2, *p_deg, *p_buck, *p_is64;
    cudaGetSymbolAddress(&p_qh, g_qh);
    cudaGetSymbolAddress(&p_kh, g_kh);
    cudaGetSymbolAddress(&p_vh, g_vh);
    cudaGetSymbolAddress(&p_s, g_s);
    cudaGetSymbolAddress(&p_h, g_h);
    cudaGetSymbolAddress(&p_xch, g_xch);
    cudaGetSymbolAddress(&p_wch, g_wch);
    cudaGetSymbolAddress(&p_wch2, g_wch2);
    cudaGetSymbolAddress(&p_deg, g_deg);
    cudaGetSymbolAddress(&p_buck, g_buck);
    cudaGetSymbolAddress(&p_is64, g_is64);

    __half* qh  = (__half*)p_qh;
    __half* kh  = (__half*)p_kh;
    __half* vh  = (__half*)p_vh;
    float*  s   = (float*)p_s;
    float*  h   = (float*)p_h;
    __half* xh  = (__half*)p_xch;
    __half* wh  = (__half*)p_wch;
    __half* wh2 = (__half*)p_wch2;
    float*  bk  = (float*)p_buck;

    cudaFuncSetAttribute(gemm4_f16_kernel<HID, IN_DIM>,
                         cudaFuncAttributeMaxDynamicSharedMemorySize, GEMM_SMEM_BYTES);
    cudaFuncSetAttribute(gemm4_f16_kernel<OUT_DIM, HID>,
                         cudaFuncAttributeMaxDynamicSharedMemorySize, GEMM_SMEM_BYTES);

    // ---- fork a side stream for the CSR build (independent of GEMM chain) ----
    cudaStream_t s2;
    cudaStreamCreateWithFlags(&s2, cudaStreamNonBlocking);
    cudaEvent_t evFork, evJoin;
    cudaEventCreateWithFlags(&evFork, cudaEventDisableTiming);
    cudaEventCreateWithFlags(&evJoin, cudaEventDisableTiming);

    cudaEventRecord(evFork, 0);
    cudaStreamWaitEvent(s2, evFork, 0);

    // side stream: edge dtype detect + CSR build
    cudaMemsetAsync(p_is64, 0xFF, sizeof(int), s2);
    detect_idx_kernel<<<1024, 256, 0, s2>>>((const long long*)ei);
    cudaMemsetAsync(p_deg, 0, N_NODES * sizeof(int), s2);
    cvt_count_kernel<<<2048, 256, 0, s2>>>(ei);
    scan_offsets_kernel<<<1, 1024, 0, s2>>>();
    fill_csr_kernel<<<2048, 256, 0, s2>>>();
    cudaEventRecord(evJoin, s2);

    // main stream: converts + layer-1 GEMM (overlaps with CSR build)
    cudaMemsetAsync(p_buck, 0, 256 * sizeof(float), 0);
    cvt_f2h_kernel<<<2048, 256>>>(x, xh, N_NODES * IN_DIM);
    {
        dim3 g(256, 4);
        cvtT4_f2h_kernel<<<g, 256>>>(Wq1, Wk1, Wv1, Ws1, wh, IN_DIM, HID);
    }
    {
        dim3 g(128, 4);
        cvtT4_f2h_kernel<<<g, 256>>>(Wq2, Wk2, Wv2, Ws2, wh2, HID, OUT_DIM);
    }
    {
        dim3 grid((N_NODES + 127) / 128, HID / 128, 4);
        gemm4_f16_kernel<HID, IN_DIM><<<grid, 256, GEMM_SMEM_BYTES>>>(
            xh, wh, bq1, bk1, bv1, bs1, qh, kh, vh, s, N_NODES);
    }

    // join: edge phase needs both GEMM outputs and CSR
    cudaStreamWaitEvent(0, evJoin, 0);

    edge_fused_kernel<HID, 8, 64><<<N_NODES, 256>>>(qh, kh, vh, s, h, bk, 1.0f / 16.0f);
    normalize_elu_h_kernel<<<2048, 256>>>(h, ga1, be1, xh, bk, HID - 1, (long)N_NODES * HID);

    // ---- layer 2 ----
    {
        dim3 grid((N_NODES + 127) / 128, OUT_DIM / 128, 4);
        gemm4_f16_kernel<OUT_DIM, HID><<<grid, 256, GEMM_SMEM_BYTES>>>(
            xh, wh2, bq2, bk2, bv2, bs2, qh, kh, vh, s, N_NODES);
    }
    edge_fused_kernel<OUT_DIM, 4, 64><<<N_NODES, 128>>>(qh, kh, vh, s, h, bk + 128,
                                                        0.08838834764831845f);
    normalize_f_kernel<<<2048, 256>>>(h, ga2, be2, out, bk + 128, OUT_DIM - 1,
                                      (long)N_NODES * OUT_DIM);

    cudaEventDestroy(evFork);
    cudaEventDestroy(evJoin);
    cudaStreamDestroy(s2);
}